// round 5
// baseline (speedup 1.0000x reference)
#include <cuda_runtime.h>
#include <math.h>
#include <stdint.h>

typedef unsigned long long u64;

#define NB   64
#define HID  512
#define VOC  32000
#define TT   50
#define NBLK_B 250
#define NKS  16
#define START_TOK 1
#define END_TOK 2

// ---------------- device scratch ----------------
__device__ float g_Wlt[HID * VOC];        // W_lin transposed [k][r]
__device__ float g_Wgt[1024 * 2048];      // gates W transposed [k][j]
__device__ float g_sv[1024 * NB];         // [512..1024) rows: h transposed [k][b]
__device__ float g_c[NB * HID];
__device__ float g_gp[NKS][NB * 2048];    // split-K gate partials
__device__ int   g_word[NB];
__device__ int   g_mask[NB];
__device__ int   g_done;
__device__ float g_pv[NBLK_B * NB];
__device__ int   g_pi[NBLK_B * NB];
__device__ unsigned int g_cnt;            // kB last-block counter

// ---------------- f32x2 helpers ----------------
__device__ __forceinline__ u64 pack2(float a, float b) {
    u64 r; asm("mov.b64 %0, {%1, %2};" : "=l"(r) : "f"(a), "f"(b)); return r;
}
__device__ __forceinline__ void unpack2(u64 v, float &a, float &b) {
    asm("mov.b64 {%0, %1}, %2;" : "=f"(a), "=f"(b) : "l"(v));
}
__device__ __forceinline__ void ffma2(u64 &d, u64 a, u64 b) {
    asm("fma.rn.f32x2 %0, %1, %2, %0;" : "+l"(d) : "l"(a), "l"(b));
}

// 4 rows x 4 batch-pairs micro-step
__device__ __forceinline__ void mstep4(u64 (&acc)[4][4], float4 w, const u64 (&h)[4]) {
    u64 wd[4];
    wd[0] = pack2(w.x, w.x); wd[1] = pack2(w.y, w.y);
    wd[2] = pack2(w.z, w.z); wd[3] = pack2(w.w, w.w);
    #pragma unroll
    for (int r = 0; r < 4; r++)
        #pragma unroll
        for (int p = 0; p < 4; p++)
            ffma2(acc[r][p], wd[r], h[p]);
}

// ---------------- weight transposes (once per replay) ----------------
__global__ void kTransL(const float* __restrict__ Wl) {
    __shared__ float tile[32][33];
    int r0 = blockIdx.x * 32, k0 = blockIdx.y * 32;
    int tx = threadIdx.x, ty = threadIdx.y;
    #pragma unroll
    for (int i = 0; i < 4; i++)
        tile[ty + 8 * i][tx] = Wl[(size_t)(r0 + ty + 8 * i) * HID + k0 + tx];
    __syncthreads();
    #pragma unroll
    for (int i = 0; i < 4; i++)
        g_Wlt[(size_t)(k0 + ty + 8 * i) * VOC + r0 + tx] = tile[tx][ty + 8 * i];
}

__global__ void kTransG(const float* __restrict__ Wih, const float* __restrict__ Whh) {
    __shared__ float tile[32][33];
    int j0 = blockIdx.x * 32, k0 = blockIdx.y * 32;
    const float* W = (k0 < 512) ? Wih : Whh;
    int kk = (k0 < 512) ? k0 : k0 - 512;
    int tx = threadIdx.x, ty = threadIdx.y;
    #pragma unroll
    for (int i = 0; i < 4; i++)
        tile[ty + 8 * i][tx] = W[(size_t)(j0 + ty + 8 * i) * 512 + kk + tx];
    __syncthreads();
    #pragma unroll
    for (int i = 0; i < 4; i++)
        g_Wgt[(size_t)(k0 + ty + 8 * i) * 2048 + j0 + tx] = tile[tx][ty + 8 * i];
}

// ---------------- init ----------------
__global__ void kInit(const float* __restrict__ feat) {
    int gid = blockIdx.x * blockDim.x + threadIdx.x;
    if (gid < NB * HID) {
        int b = gid >> 9, u = gid & 511;
        g_c[gid] = 0.f;
        g_sv[(512 + u) * 64 + b] = feat[gid];
    }
    if (gid < NB) { g_word[gid] = START_TOK; g_mask[gid] = 0; }
    if (gid == 0) { g_done = 0; g_cnt = 0u; }
}

// ---------------- kGates: split-K gates GEMM --------------------------
// grid (16,16): x -> 128 gate rows, y = 64-k slice. ks<8: x=emb[word], else h.
__global__ __launch_bounds__(256) void kGates(const float* __restrict__ emb) {
    if (g_done) return;
    const int tid = threadIdx.x, lane = tid & 31, wid = tid >> 5;
    const int ks = blockIdx.y;
    const int r0 = blockIdx.x * 128 + lane * 4;
    const int b0 = wid * 8;
    const int kb = ks * 64;

    u64 acc[4][4];
    #pragma unroll
    for (int r = 0; r < 4; r++)
        #pragma unroll
        for (int p = 0; p < 4; p++) acc[r][p] = 0ull;

    const float4* wp = reinterpret_cast<const float4*>(g_Wgt + (size_t)kb * 2048 + r0);

    if (ks < 8) {
        const float* xr[8];
        #pragma unroll
        for (int j = 0; j < 8; j++)
            xr[j] = emb + (size_t)g_word[b0 + j] * 512 + kb;
        float4 wa = wp[0], wb = wp[512]; wp += 1024;
        for (int k = 0; k < 62; k += 2) {
            float4 wna = wp[0], wnb = wp[512]; wp += 1024;
            u64 h0[4], h1[4];
            #pragma unroll
            for (int p = 0; p < 4; p++) {
                h0[p] = pack2(xr[2 * p][k],     xr[2 * p + 1][k]);
                h1[p] = pack2(xr[2 * p][k + 1], xr[2 * p + 1][k + 1]);
            }
            mstep4(acc, wa, h0); mstep4(acc, wb, h1);
            wa = wna; wb = wnb;
        }
        {
            u64 h0[4], h1[4];
            #pragma unroll
            for (int p = 0; p < 4; p++) {
                h0[p] = pack2(xr[2 * p][62], xr[2 * p + 1][62]);
                h1[p] = pack2(xr[2 * p][63], xr[2 * p + 1][63]);
            }
            mstep4(acc, wa, h0); mstep4(acc, wb, h1);
        }
    } else {
        const u64* hp = reinterpret_cast<const u64*>(g_sv + (size_t)kb * 64) + (b0 >> 1);
        float4 wa = wp[0], wb = wp[512]; wp += 1024;
        for (int k = 0; k < 62; k += 2) {
            float4 wna = wp[0], wnb = wp[512]; wp += 1024;
            u64 h0[4], h1[4];
            #pragma unroll
            for (int p = 0; p < 4; p++) { h0[p] = hp[p]; h1[p] = hp[32 + p]; }
            hp += 64;
            mstep4(acc, wa, h0); mstep4(acc, wb, h1);
            wa = wna; wb = wnb;
        }
        {
            u64 h0[4], h1[4];
            #pragma unroll
            for (int p = 0; p < 4; p++) { h0[p] = hp[p]; h1[p] = hp[32 + p]; }
            mstep4(acc, wa, h0); mstep4(acc, wb, h1);
        }
    }

    #pragma unroll
    for (int p = 0; p < 4; p++) {
        float va[4], vb[4];
        #pragma unroll
        for (int r = 0; r < 4; r++) unpack2(acc[r][p], va[r], vb[r]);
        *reinterpret_cast<float4*>(&g_gp[ks][(b0 + 2 * p) * 2048 + r0]) =
            make_float4(va[0], va[1], va[2], va[3]);
        *reinterpret_cast<float4*>(&g_gp[ks][(b0 + 2 * p + 1) * 2048 + r0]) =
            make_float4(vb[0], vb[1], vb[2], vb[3]);
    }
}

// ---------------- kPoint: sum split-K partials + bias + LSTM pointwise ----
__global__ void kPoint(const float* __restrict__ bih, const float* __restrict__ bhh) {
    if (g_done) return;
    int gid = blockIdx.x * blockDim.x + threadIdx.x;
    int b = gid >> 9, u = gid & 511;
    float gate[4];
    #pragma unroll
    for (int q = 0; q < 4; q++) {
        int j = u + 512 * q;
        float s = bih[j] + bhh[j];
        #pragma unroll
        for (int ks = 0; ks < NKS; ks++) s += g_gp[ks][b * 2048 + j];
        gate[q] = s;
    }
    float ii = 1.f / (1.f + expf(-gate[0]));
    float ff = 1.f / (1.f + expf(-gate[1]));
    float gg = tanhf(gate[2]);
    float oo = 1.f / (1.f + expf(-gate[3]));
    float c = ff * g_c[gid] + ii * gg;
    g_c[gid] = c;
    g_sv[(512 + u) * 64 + b] = oo * tanhf(c);
}

// ---------------- kB: logits GEMM + argmax + store + fused finalize ----
// grid 250: block = 128 vocab rows x 64 batches. lane -> 4 rows, warp -> 8 batches.
__global__ __launch_bounds__(256) void kB(const float* __restrict__ bl,
                                          float* __restrict__ out, int t) {
    const int tid = threadIdx.x, lane = tid & 31, wid = tid >> 5;
    const int blk = blockIdx.x;
    const int r0 = blk * 128 + lane * 4;
    const int b0 = wid * 8;

    if (g_done) {
        for (int idx = tid; idx < 128 * 64; idx += 256) {
            int b = idx >> 7, r = idx & 127;
            out[(size_t)b * (TT * VOC) + (size_t)t * VOC + blk * 128 + r] = 0.f;
        }
        return;
    }

    u64 acc[4][4];
    #pragma unroll
    for (int r = 0; r < 4; r++)
        #pragma unroll
        for (int p = 0; p < 4; p++) acc[r][p] = 0ull;

    const float4* wp = reinterpret_cast<const float4*>(g_Wlt + r0);     // +8000 f4/k
    const u64* hp = reinterpret_cast<const u64*>(g_sv + 512 * 64) + (b0 >> 1);

    float4 wa = wp[0], wb = wp[8000]; wp += 16000;
    for (int k = 0; k < 510; k += 2) {
        float4 wna = wp[0], wnb = wp[8000]; wp += 16000;
        u64 h0[4], h1[4];
        #pragma unroll
        for (int p = 0; p < 4; p++) { h0[p] = hp[p]; h1[p] = hp[32 + p]; }
        hp += 64;
        mstep4(acc, wa, h0); mstep4(acc, wb, h1);
        wa = wna; wb = wnb;
    }
    {
        u64 h0[4], h1[4];
        #pragma unroll
        for (int p = 0; p < 4; p++) { h0[p] = hp[p]; h1[p] = hp[32 + p]; }
        mstep4(acc, wa, h0); mstep4(acc, wb, h1);
    }

    float4 bv = *reinterpret_cast<const float4*>(bl + r0);
    float bias[4] = {bv.x, bv.y, bv.z, bv.w};

    #pragma unroll
    for (int p = 0; p < 4; p++) {
        float va[4], vbv[4];
        #pragma unroll
        for (int r = 0; r < 4; r++) {
            float a, b_; unpack2(acc[r][p], a, b_);
            va[r] = a + bias[r]; vbv[r] = b_ + bias[r];
        }
        #pragma unroll
        for (int half = 0; half < 2; half++) {
            const float* v = half ? vbv : va;
            int b = b0 + 2 * p + half;
            float bestv = v[0]; int besti = r0;
            #pragma unroll
            for (int i = 1; i < 4; i++)
                if (v[i] > bestv) { bestv = v[i]; besti = r0 + i; }
            #pragma unroll
            for (int s = 16; s > 0; s >>= 1) {
                float ov = __shfl_xor_sync(0xffffffffu, bestv, s);
                int   oi = __shfl_xor_sync(0xffffffffu, besti, s);
                if (ov > bestv || (ov == bestv && oi < besti)) { bestv = ov; besti = oi; }
            }
            if (lane == 0) { g_pv[blk * 64 + b] = bestv; g_pi[blk * 64 + b] = besti; }
            float* op = out + (size_t)b * (TT * VOC) + (size_t)t * VOC + r0;
            *reinterpret_cast<float4*>(op) = make_float4(v[0], v[1], v[2], v[3]);
        }
    }

    // ---- fused argmax finalize: last block does kC's work ----
    __shared__ unsigned int s_last;
    __threadfence();
    __syncthreads();
    if (tid == 0) {
        unsigned int old = atomicAdd(&g_cnt, 1u);
        s_last = (old == NBLK_B - 1) ? 1u : 0u;
    }
    __syncthreads();
    if (!s_last) return;
    __threadfence();    // acquire all blocks' g_pv/g_pi

    __shared__ float sv[256];
    __shared__ int   si[256];
    __shared__ int   sm[64];
    {
        int b = tid & 63, q = tid >> 6;
        int s = q * 63, e = (s + 63 < NBLK_B) ? s + 63 : NBLK_B;
        float best = -1e30f; int bi = 0x7fffffff;
        for (int kk = s; kk < e; kk++) {
            float v = g_pv[kk * 64 + b];
            int   i = g_pi[kk * 64 + b];
            if (v > best || (v == best && i < bi)) { best = v; bi = i; }
        }
        sv[q * 64 + b] = best; si[q * 64 + b] = bi;
    }
    __syncthreads();
    if (tid < 64) {
        float bvv = sv[tid]; int bix = si[tid];
        #pragma unroll
        for (int q2 = 1; q2 < 4; q2++) {
            float v = sv[q2 * 64 + tid]; int i = si[q2 * 64 + tid];
            if (v > bvv || (v == bvv && i < bix)) { bvv = v; bix = i; }
        }
        g_word[tid] = bix;
        int m = g_mask[tid] | (bix == END_TOK);
        g_mask[tid] = m;
        sm[tid] = m;
    }
    __syncthreads();
    if (tid == 0) {
        int all = 1;
        for (int b2 = 0; b2 < 64; b2++) all &= sm[b2];
        if (all) g_done = 1;
        g_cnt = 0u;
    }
}

extern "C" void kernel_launch(void* const* d_in, const int* in_sizes, int n_in,
                              void* d_out, int out_size) {
    const float* feat = (const float*)d_in[0];
    const float* emb  = (const float*)d_in[1];
    const float* Wih  = (const float*)d_in[2];
    const float* Whh  = (const float*)d_in[3];
    const float* bih  = (const float*)d_in[4];
    const float* bhh  = (const float*)d_in[5];
    const float* Wl   = (const float*)d_in[6];
    const float* bl   = (const float*)d_in[7];
    float* out = (float*)d_out;

    kTransL<<<dim3(1000, 16), dim3(32, 8)>>>(Wl);
    kTransG<<<dim3(64, 32), dim3(32, 8)>>>(Wih, Whh);
    kInit<<<128, 256>>>(feat);
    for (int t = 0; t < TT; t++) {
        kGates<<<dim3(16, 16), 256>>>(emb);
        kPoint<<<64, 512>>>(bih, bhh);
        kB<<<NBLK_B, 256>>>(bl, out, t);
    }
}

// round 6
// speedup vs baseline: 1.1949x; 1.1949x over previous
#include <cuda_runtime.h>
#include <math.h>
#include <stdint.h>

typedef unsigned long long u64;

#define NB   64
#define HID  512
#define VOC  32000
#define TT   50
#define NBLK_B 125
#define NPART  250
#define NKS  16
#define START_TOK 1
#define END_TOK 2

// ---------------- device scratch ----------------
__device__ float g_Wlt[HID * VOC];        // W_lin transposed [k][r]
__device__ float g_Wgt[1024 * 2048];      // gates W transposed [k][j]
__device__ float g_sv[1024 * NB];         // [512..1024) rows: h transposed [k][b]
__device__ float g_c[NB * HID];
__device__ float g_gp[NKS][NB * 2048];    // split-K gate partials
__device__ int   g_word[NB];
__device__ int   g_mask[NB];
__device__ int   g_done;
__device__ float g_pv[NPART * NB];
__device__ int   g_pi[NPART * NB];

// ---------------- f32x2 helpers ----------------
__device__ __forceinline__ u64 pack2(float a, float b) {
    u64 r; asm("mov.b64 %0, {%1, %2};" : "=l"(r) : "f"(a), "f"(b)); return r;
}
__device__ __forceinline__ void unpack2(u64 v, float &a, float &b) {
    asm("mov.b64 {%0, %1}, %2;" : "=f"(a), "=f"(b) : "l"(v));
}
__device__ __forceinline__ void ffma2(u64 &d, u64 a, u64 b) {
    asm("fma.rn.f32x2 %0, %1, %2, %0;" : "+l"(d) : "l"(a), "l"(b));
}

// 4 rows x 4 batch-pairs micro-step
__device__ __forceinline__ void mstep4(u64 (&acc)[4][4], float4 w, const u64 (&h)[4]) {
    u64 wd[4];
    wd[0] = pack2(w.x, w.x); wd[1] = pack2(w.y, w.y);
    wd[2] = pack2(w.z, w.z); wd[3] = pack2(w.w, w.w);
    #pragma unroll
    for (int r = 0; r < 4; r++)
        #pragma unroll
        for (int p = 0; p < 4; p++)
            ffma2(acc[r][p], wd[r], h[p]);
}

// ---------------- weight transposes (once per replay) ----------------
__global__ void kTransL(const float* __restrict__ Wl) {
    __shared__ float tile[32][33];
    int r0 = blockIdx.x * 32, k0 = blockIdx.y * 32;
    int tx = threadIdx.x, ty = threadIdx.y;
    #pragma unroll
    for (int i = 0; i < 4; i++)
        tile[ty + 8 * i][tx] = Wl[(size_t)(r0 + ty + 8 * i) * HID + k0 + tx];
    __syncthreads();
    #pragma unroll
    for (int i = 0; i < 4; i++)
        g_Wlt[(size_t)(k0 + ty + 8 * i) * VOC + r0 + tx] = tile[tx][ty + 8 * i];
}

__global__ void kTransG(const float* __restrict__ Wih, const float* __restrict__ Whh) {
    __shared__ float tile[32][33];
    int j0 = blockIdx.x * 32, k0 = blockIdx.y * 32;
    const float* W = (k0 < 512) ? Wih : Whh;
    int kk = (k0 < 512) ? k0 : k0 - 512;
    int tx = threadIdx.x, ty = threadIdx.y;
    #pragma unroll
    for (int i = 0; i < 4; i++)
        tile[ty + 8 * i][tx] = W[(size_t)(j0 + ty + 8 * i) * 512 + kk + tx];
    __syncthreads();
    #pragma unroll
    for (int i = 0; i < 4; i++)
        g_Wgt[(size_t)(k0 + ty + 8 * i) * 2048 + j0 + tx] = tile[tx][ty + 8 * i];
}

// ---------------- init ----------------
__global__ void kInit(const float* __restrict__ feat) {
    int gid = blockIdx.x * blockDim.x + threadIdx.x;
    if (gid < NB * HID) {
        int b = gid >> 9, u = gid & 511;
        g_c[gid] = 0.f;
        g_sv[(512 + u) * 64 + b] = feat[gid];
    }
    if (gid < NB) { g_word[gid] = START_TOK; g_mask[gid] = 0; }
    if (gid == 0)   g_done = 0;
}

// ---------------- kGates: split-K gates GEMM --------------------------
// grid (8,16): x -> 256 gate rows, y = 64-k slice; 512 threads.
// warp: batches (wid&7)*8, rows x*256 + (wid>>3)*128 + lane*4.
__global__ __launch_bounds__(512) void kGates(const float* __restrict__ emb) {
    if (g_done) return;
    const int tid = threadIdx.x, lane = tid & 31, wid = tid >> 5;
    const int ks = blockIdx.y;
    const int r0 = blockIdx.x * 256 + (wid >> 3) * 128 + lane * 4;
    const int b0 = (wid & 7) * 8;
    const int kb = ks * 64;

    u64 acc[4][4];
    #pragma unroll
    for (int r = 0; r < 4; r++)
        #pragma unroll
        for (int p = 0; p < 4; p++) acc[r][p] = 0ull;

    const float4* wp = reinterpret_cast<const float4*>(g_Wgt + (size_t)kb * 2048 + r0);

    if (ks < 8) {
        const float* xr[8];
        #pragma unroll
        for (int j = 0; j < 8; j++)
            xr[j] = emb + (size_t)g_word[b0 + j] * 512 + kb;
        float4 wa = wp[0], wb = wp[512]; wp += 1024;
        u64 h0[4], h1[4];
        #pragma unroll
        for (int p = 0; p < 4; p++) {
            h0[p] = pack2(xr[2 * p][0], xr[2 * p + 1][0]);
            h1[p] = pack2(xr[2 * p][1], xr[2 * p + 1][1]);
        }
        for (int k = 2; k < 64; k += 2) {
            float4 wna = wp[0], wnb = wp[512]; wp += 1024;
            u64 h0n[4], h1n[4];
            #pragma unroll
            for (int p = 0; p < 4; p++) {
                h0n[p] = pack2(xr[2 * p][k],     xr[2 * p + 1][k]);
                h1n[p] = pack2(xr[2 * p][k + 1], xr[2 * p + 1][k + 1]);
            }
            mstep4(acc, wa, h0); mstep4(acc, wb, h1);
            wa = wna; wb = wnb;
            #pragma unroll
            for (int p = 0; p < 4; p++) { h0[p] = h0n[p]; h1[p] = h1n[p]; }
        }
        mstep4(acc, wa, h0); mstep4(acc, wb, h1);
    } else {
        const u64* hp = reinterpret_cast<const u64*>(g_sv + (size_t)kb * 64) + (b0 >> 1);
        float4 wa = wp[0], wb = wp[512]; wp += 1024;
        u64 h0[4], h1[4];
        #pragma unroll
        for (int p = 0; p < 4; p++) { h0[p] = hp[p]; h1[p] = hp[32 + p]; }
        hp += 64;
        for (int k = 2; k < 64; k += 2) {
            float4 wna = wp[0], wnb = wp[512]; wp += 1024;
            u64 h0n[4], h1n[4];
            #pragma unroll
            for (int p = 0; p < 4; p++) { h0n[p] = hp[p]; h1n[p] = hp[32 + p]; }
            hp += 64;
            mstep4(acc, wa, h0); mstep4(acc, wb, h1);
            wa = wna; wb = wnb;
            #pragma unroll
            for (int p = 0; p < 4; p++) { h0[p] = h0n[p]; h1[p] = h1n[p]; }
        }
        mstep4(acc, wa, h0); mstep4(acc, wb, h1);
    }

    #pragma unroll
    for (int p = 0; p < 4; p++) {
        float va[4], vb[4];
        #pragma unroll
        for (int r = 0; r < 4; r++) unpack2(acc[r][p], va[r], vb[r]);
        *reinterpret_cast<float4*>(&g_gp[ks][(b0 + 2 * p) * 2048 + r0]) =
            make_float4(va[0], va[1], va[2], va[3]);
        *reinterpret_cast<float4*>(&g_gp[ks][(b0 + 2 * p + 1) * 2048 + r0]) =
            make_float4(vb[0], vb[1], vb[2], vb[3]);
    }
}

// ---------------- kPoint: sum split-K partials + bias + LSTM pointwise ----
__global__ void kPoint(const float* __restrict__ bih, const float* __restrict__ bhh) {
    if (g_done) return;
    int gid = blockIdx.x * blockDim.x + threadIdx.x;
    int b = gid >> 9, u = gid & 511;
    float gate[4];
    #pragma unroll
    for (int q = 0; q < 4; q++) {
        int j = u + 512 * q;
        float s = bih[j] + bhh[j];
        #pragma unroll
        for (int ks = 0; ks < NKS; ks++) s += g_gp[ks][b * 2048 + j];
        gate[q] = s;
    }
    float ii = 1.f / (1.f + expf(-gate[0]));
    float ff = 1.f / (1.f + expf(-gate[1]));
    float gg = tanhf(gate[2]);
    float oo = 1.f / (1.f + expf(-gate[3]));
    float c = ff * g_c[gid] + ii * gg;
    g_c[gid] = c;
    g_sv[(512 + u) * 64 + b] = oo * tanhf(c);
}

// ---------------- kB: logits GEMM + bias + partial argmax + store ----
// grid 125, 512 threads: block = 256 vocab rows x 64 batches.
// warp: batches (wid&7)*8, rows blk*256 + (wid>>3)*128 + lane*4.
__global__ __launch_bounds__(512) void kB(const float* __restrict__ bl,
                                          float* __restrict__ out, int t) {
    const int tid = threadIdx.x, lane = tid & 31, wid = tid >> 5;
    const int blk = blockIdx.x;
    const int half_blk = wid >> 3;
    const int r0 = blk * 256 + half_blk * 128 + lane * 4;
    const int b0 = (wid & 7) * 8;

    if (g_done) {
        for (int idx = tid; idx < 256 * 64; idx += 512) {
            int b = idx >> 8, r = idx & 255;
            out[(size_t)b * (TT * VOC) + (size_t)t * VOC + blk * 256 + r] = 0.f;
        }
        return;
    }

    u64 acc[4][4];
    #pragma unroll
    for (int r = 0; r < 4; r++)
        #pragma unroll
        for (int p = 0; p < 4; p++) acc[r][p] = 0ull;

    const float4* wp = reinterpret_cast<const float4*>(g_Wlt + r0);     // +8000 f4/k
    const u64* hp = reinterpret_cast<const u64*>(g_sv + 512 * 64) + (b0 >> 1);

    float4 wa = wp[0], wb = wp[8000]; wp += 16000;
    u64 h0[4], h1[4];
    #pragma unroll
    for (int p = 0; p < 4; p++) { h0[p] = hp[p]; h1[p] = hp[32 + p]; }
    hp += 64;
    for (int k = 2; k < 512; k += 2) {
        float4 wna = wp[0], wnb = wp[8000]; wp += 16000;
        u64 h0n[4], h1n[4];
        #pragma unroll
        for (int p = 0; p < 4; p++) { h0n[p] = hp[p]; h1n[p] = hp[32 + p]; }
        hp += 64;
        mstep4(acc, wa, h0); mstep4(acc, wb, h1);
        wa = wna; wb = wnb;
        #pragma unroll
        for (int p = 0; p < 4; p++) { h0[p] = h0n[p]; h1[p] = h1n[p]; }
    }
    mstep4(acc, wa, h0); mstep4(acc, wb, h1);

    float4 bv = *reinterpret_cast<const float4*>(bl + r0);
    float bias[4] = {bv.x, bv.y, bv.z, bv.w};
    const int part = blk * 2 + half_blk;

    #pragma unroll
    for (int p = 0; p < 4; p++) {
        float va[4], vbv[4];
        #pragma unroll
        for (int r = 0; r < 4; r++) {
            float a, b_; unpack2(acc[r][p], a, b_);
            va[r] = a + bias[r]; vbv[r] = b_ + bias[r];
        }
        #pragma unroll
        for (int half = 0; half < 2; half++) {
            const float* v = half ? vbv : va;
            int b = b0 + 2 * p + half;
            float bestv = v[0]; int besti = r0;
            #pragma unroll
            for (int i = 1; i < 4; i++)
                if (v[i] > bestv) { bestv = v[i]; besti = r0 + i; }
            #pragma unroll
            for (int s = 16; s > 0; s >>= 1) {
                float ov = __shfl_xor_sync(0xffffffffu, bestv, s);
                int   oi = __shfl_xor_sync(0xffffffffu, besti, s);
                if (ov > bestv || (ov == bestv && oi < besti)) { bestv = ov; besti = oi; }
            }
            if (lane == 0) { g_pv[part * 64 + b] = bestv; g_pi[part * 64 + b] = besti; }
            float* op = out + (size_t)b * (TT * VOC) + (size_t)t * VOC + r0;
            *reinterpret_cast<float4*>(op) = make_float4(v[0], v[1], v[2], v[3]);
        }
    }
}

// ---------------- kC: argmax finalize, word/mask/done update ----------------
__global__ void kC() {
    if (g_done) return;
    __shared__ float sv[256];
    __shared__ int   si[256];
    __shared__ int   sm[64];
    int tid = threadIdx.x;
    int b = tid & 63, q = tid >> 6;
    int s = q * 63, e = (s + 63 < NPART) ? s + 63 : NPART;
    float best = -1e30f; int bi = 0x7fffffff;
    for (int k = s; k < e; k++) {
        float v = g_pv[k * 64 + b];
        int   i = g_pi[k * 64 + b];
        if (v > best || (v == best && i < bi)) { best = v; bi = i; }
    }
    sv[q * 64 + b] = best; si[q * 64 + b] = bi;
    __syncthreads();
    if (tid < 64) {
        float bvv = sv[tid]; int bix = si[tid];
        #pragma unroll
        for (int q2 = 1; q2 < 4; q2++) {
            float v = sv[q2 * 64 + tid]; int i = si[q2 * 64 + tid];
            if (v > bvv || (v == bvv && i < bix)) { bvv = v; bix = i; }
        }
        g_word[tid] = bix;
        int m = g_mask[tid] | (bix == END_TOK);
        g_mask[tid] = m;
        sm[tid] = m;
    }
    __syncthreads();
    if (tid == 0) {
        int all = 1;
        for (int b2 = 0; b2 < 64; b2++) all &= sm[b2];
        if (all) g_done = 1;
    }
}

extern "C" void kernel_launch(void* const* d_in, const int* in_sizes, int n_in,
                              void* d_out, int out_size) {
    const float* feat = (const float*)d_in[0];
    const float* emb  = (const float*)d_in[1];
    const float* Wih  = (const float*)d_in[2];
    const float* Whh  = (const float*)d_in[3];
    const float* bih  = (const float*)d_in[4];
    const float* bhh  = (const float*)d_in[5];
    const float* Wl   = (const float*)d_in[6];
    const float* bl   = (const float*)d_in[7];
    float* out = (float*)d_out;

    kTransL<<<dim3(1000, 16), dim3(32, 8)>>>(Wl);
    kTransG<<<dim3(64, 32), dim3(32, 8)>>>(Wih, Whh);
    kInit<<<128, 256>>>(feat);
    for (int t = 0; t < TT; t++) {
        kGates<<<dim3(8, 16), 512>>>(emb);
        kPoint<<<64, 512>>>(bih, bhh);
        kB<<<NBLK_B, 512>>>(bl, out, t);
        kC<<<1, 256>>>();
    }
}

// round 7
// speedup vs baseline: 1.3799x; 1.1548x over previous
#include <cuda_runtime.h>
#include <math.h>
#include <stdint.h>

typedef unsigned long long u64;

#define NB    64
#define HID   512
#define VOC   32000
#define TT    50
#define NBLK_B 125
#define NPART 250
#define NKS   16
#define START_TOK 1
#define END_TOK 2
#define CHUNK 256

// ---------------- device scratch ----------------
__device__ float g_Wlt[(HID + 8) * VOC];     // W_lin transposed [k][r], padded rows
__device__ float g_Wgt[(1024 + 8) * 2048];   // gates W transposed [k][j], padded
__device__ float g_sv[HID * NB];             // h transposed [k][b]
__device__ float g_c[NB * HID];
__device__ float g_gp[NKS][NB * 2048];       // split-K gate partials
__device__ int   g_word[NB];
__device__ int   g_mask[NB];
__device__ int   g_done;
__device__ float g_pv[NPART * NB];
__device__ int   g_pi[NPART * NB];

// ---------------- helpers ----------------
__device__ __forceinline__ void unpack2(u64 v, float &a, float &b) {
    asm("mov.b64 {%0, %1}, %2;" : "=f"(a), "=f"(b) : "l"(v));
}
__device__ __forceinline__ void ffma2(u64 &d, u64 a, u64 b) {
    asm("fma.rn.f32x2 %0, %1, %2, %0;" : "+l"(d) : "l"(a), "l"(b));
}

// one k-step: w = 2 row-pairs (4 rows), sh -> 8 duplicated batch values
__device__ __forceinline__ void bodyk(u64 (&acc)[2][8], ulonglong2 w, const float* sh) {
    ulonglong2 h0 = *reinterpret_cast<const ulonglong2*>(sh);
    ulonglong2 h1 = *reinterpret_cast<const ulonglong2*>(sh + 4);
    ulonglong2 h2 = *reinterpret_cast<const ulonglong2*>(sh + 8);
    ulonglong2 h3 = *reinterpret_cast<const ulonglong2*>(sh + 12);
    ffma2(acc[0][0], w.x, h0.x); ffma2(acc[1][0], w.y, h0.x);
    ffma2(acc[0][1], w.x, h0.y); ffma2(acc[1][1], w.y, h0.y);
    ffma2(acc[0][2], w.x, h1.x); ffma2(acc[1][2], w.y, h1.x);
    ffma2(acc[0][3], w.x, h1.y); ffma2(acc[1][3], w.y, h1.y);
    ffma2(acc[0][4], w.x, h2.x); ffma2(acc[1][4], w.y, h2.x);
    ffma2(acc[0][5], w.x, h2.y); ffma2(acc[1][5], w.y, h2.y);
    ffma2(acc[0][6], w.x, h3.x); ffma2(acc[1][6], w.y, h3.x);
    ffma2(acc[0][7], w.x, h3.y); ffma2(acc[1][7], w.y, h3.y);
}

// ---------------- weight transposes (once per replay) ----------------
__global__ void kTransL(const float* __restrict__ Wl) {
    __shared__ float tile[32][33];
    int r0 = blockIdx.x * 32, k0 = blockIdx.y * 32;
    int tx = threadIdx.x, ty = threadIdx.y;
    #pragma unroll
    for (int i = 0; i < 4; i++)
        tile[ty + 8 * i][tx] = Wl[(size_t)(r0 + ty + 8 * i) * HID + k0 + tx];
    __syncthreads();
    #pragma unroll
    for (int i = 0; i < 4; i++)
        g_Wlt[(size_t)(k0 + ty + 8 * i) * VOC + r0 + tx] = tile[tx][ty + 8 * i];
}

__global__ void kTransG(const float* __restrict__ Wih, const float* __restrict__ Whh) {
    __shared__ float tile[32][33];
    int j0 = blockIdx.x * 32, k0 = blockIdx.y * 32;
    const float* W = (k0 < 512) ? Wih : Whh;
    int kk = (k0 < 512) ? k0 : k0 - 512;
    int tx = threadIdx.x, ty = threadIdx.y;
    #pragma unroll
    for (int i = 0; i < 4; i++)
        tile[ty + 8 * i][tx] = W[(size_t)(j0 + ty + 8 * i) * 512 + kk + tx];
    __syncthreads();
    #pragma unroll
    for (int i = 0; i < 4; i++)
        g_Wgt[(size_t)(k0 + ty + 8 * i) * 2048 + j0 + tx] = tile[tx][ty + 8 * i];
}

// ---------------- init ----------------
__global__ void kInit(const float* __restrict__ feat) {
    int gid = blockIdx.x * blockDim.x + threadIdx.x;   // 64 blocks * 512
    int b = gid >> 9, u = gid & 511;
    g_c[b * 512 + u] = 0.f;
    g_sv[u * 64 + b] = feat[b * 512 + u];
    if (gid < NB) { g_word[gid] = START_TOK; g_mask[gid] = 0; }
    if (gid == 0)   g_done = 0;
}

// ---------------- kGates: split-K gates GEMM --------------------------
// grid (8,16): x -> 256 gate rows, y = 64-k slice; 512 threads.
// ks<8: source = emb[word] (gathered into smem), else h from g_sv.
__global__ __launch_bounds__(512) void kGates(const float* __restrict__ emb) {
    __shared__ __align__(16) float s_hd[64 * 128];    // dup source [k][2b]
    if (g_done) return;
    const int tid = threadIdx.x, lane = tid & 31, wid = tid >> 5;
    const int ks = blockIdx.y;
    const int kb = ks * 64;
    const int r0 = blockIdx.x * 256 + (wid >> 3) * 128 + lane * 4;
    const int b0 = (wid & 7) * 8;

    if (ks < 8) {   // gather emb rows for this k-slice, duplicated
        for (int idx = tid; idx < 64 * 16; idx += 512) {
            int k = idx >> 4, g = idx & 15;
            float4 v;
            v.x = emb[(size_t)g_word[4 * g + 0] * 512 + kb + k];
            v.y = emb[(size_t)g_word[4 * g + 1] * 512 + kb + k];
            v.z = emb[(size_t)g_word[4 * g + 2] * 512 + kb + k];
            v.w = emb[(size_t)g_word[4 * g + 3] * 512 + kb + k];
            float2* d = reinterpret_cast<float2*>(&s_hd[k * 128 + g * 8]);
            d[0] = make_float2(v.x, v.x); d[1] = make_float2(v.y, v.y);
            d[2] = make_float2(v.z, v.z); d[3] = make_float2(v.w, v.w);
        }
    } else {
        for (int idx = tid; idx < 64 * 16; idx += 512) {
            int k = idx >> 4, g = idx & 15;
            float4 v = *reinterpret_cast<const float4*>(&g_sv[(kb - 512 + k) * 64 + g * 4]);
            float2* d = reinterpret_cast<float2*>(&s_hd[k * 128 + g * 8]);
            d[0] = make_float2(v.x, v.x); d[1] = make_float2(v.y, v.y);
            d[2] = make_float2(v.z, v.z); d[3] = make_float2(v.w, v.w);
        }
    }
    __syncthreads();

    u64 acc[2][8];
    #pragma unroll
    for (int r = 0; r < 2; r++)
        #pragma unroll
        for (int b = 0; b < 8; b++) acc[r][b] = 0ull;

    const float* wp = g_Wgt + (size_t)kb * 2048 + r0;
    const float* shp = s_hd + 2 * b0;
    // depth-4 W prefetch
    ulonglong2 w0 = *reinterpret_cast<const ulonglong2*>(wp);
    ulonglong2 w1 = *reinterpret_cast<const ulonglong2*>(wp + 2048);
    ulonglong2 w2 = *reinterpret_cast<const ulonglong2*>(wp + 2 * 2048);
    ulonglong2 w3 = *reinterpret_cast<const ulonglong2*>(wp + 3 * 2048);
    #pragma unroll 2
    for (int k = 0; k < 64; k += 4) {
        ulonglong2 n0 = *reinterpret_cast<const ulonglong2*>(wp + 4 * 2048);
        ulonglong2 n1 = *reinterpret_cast<const ulonglong2*>(wp + 5 * 2048);
        ulonglong2 n2 = *reinterpret_cast<const ulonglong2*>(wp + 6 * 2048);
        ulonglong2 n3 = *reinterpret_cast<const ulonglong2*>(wp + 7 * 2048);
        wp += 4 * 2048;
        bodyk(acc, w0, shp);
        bodyk(acc, w1, shp + 128);
        bodyk(acc, w2, shp + 256);
        bodyk(acc, w3, shp + 384);
        shp += 512;
        w0 = n0; w1 = n1; w2 = n2; w3 = n3;
    }

    #pragma unroll
    for (int b = 0; b < 8; b++) {
        float v0, v1, v2, v3;
        unpack2(acc[0][b], v0, v1);
        unpack2(acc[1][b], v2, v3);
        *reinterpret_cast<float4*>(&g_gp[ks][(b0 + b) * 2048 + r0]) =
            make_float4(v0, v1, v2, v3);
    }
}

// ---------------- kPoint: sum split-K partials + bias + LSTM pointwise ----
__global__ void kPoint(const float* __restrict__ bih, const float* __restrict__ bhh) {
    if (g_done) return;
    int gid = blockIdx.x * blockDim.x + threadIdx.x;   // 64 x 512
    int b = gid >> 9, u = gid & 511;
    float gate[4];
    #pragma unroll
    for (int q = 0; q < 4; q++) {
        int j = u + 512 * q;
        float s = bih[j] + bhh[j];
        #pragma unroll
        for (int ks = 0; ks < NKS; ks++) s += g_gp[ks][b * 2048 + j];
        gate[q] = s;
    }
    float ii = 1.f / (1.f + expf(-gate[0]));
    float ff = 1.f / (1.f + expf(-gate[1]));
    float gg = tanhf(gate[2]);
    float oo = 1.f / (1.f + expf(-gate[3]));
    float c = ff * g_c[gid] + ii * gg;
    g_c[gid] = c;
    g_sv[u * 64 + b] = oo * tanhf(c);
}

// ---------------- kB: logits GEMM + bias + partial argmax + store ----
// grid 125 x 512 thr: block = 256 vocab rows x 64 batches, 2 smem k-chunks of 256.
__global__ __launch_bounds__(512) void kB(const float* __restrict__ bl,
                                          float* __restrict__ out, int t) {
    extern __shared__ float s_hd[];          // [CHUNK][128] duplicated h
    const int tid = threadIdx.x, lane = tid & 31, wid = tid >> 5;
    const int blk = blockIdx.x;
    const int half = wid >> 3;
    const int r0 = blk * 256 + half * 128 + lane * 4;
    const int b0 = (wid & 7) * 8;

    if (g_done) {
        for (int idx = tid; idx < 256 * 64; idx += 512) {
            int b = idx >> 8, r = idx & 255;
            out[(size_t)b * (TT * VOC) + (size_t)t * VOC + blk * 256 + r] = 0.f;
        }
        return;
    }

    u64 acc[2][8];
    #pragma unroll
    for (int r = 0; r < 2; r++)
        #pragma unroll
        for (int b = 0; b < 8; b++) acc[r][b] = 0ull;

    const float* wbase = g_Wlt + r0;

    for (int ch = 0; ch < 2; ch++) {
        if (ch) __syncthreads();
        for (int idx = tid; idx < CHUNK * 16; idx += 512) {
            int k = idx >> 4, g = idx & 15;
            float4 v = *reinterpret_cast<const float4*>(&g_sv[(ch * CHUNK + k) * 64 + g * 4]);
            float2* d = reinterpret_cast<float2*>(&s_hd[k * 128 + g * 8]);
            d[0] = make_float2(v.x, v.x); d[1] = make_float2(v.y, v.y);
            d[2] = make_float2(v.z, v.z); d[3] = make_float2(v.w, v.w);
        }
        __syncthreads();

        const float* wp = wbase + (size_t)ch * CHUNK * VOC;
        const float* shp = s_hd + 2 * b0;
        ulonglong2 w0 = *reinterpret_cast<const ulonglong2*>(wp);
        ulonglong2 w1 = *reinterpret_cast<const ulonglong2*>(wp + VOC);
        ulonglong2 w2 = *reinterpret_cast<const ulonglong2*>(wp + 2 * VOC);
        ulonglong2 w3 = *reinterpret_cast<const ulonglong2*>(wp + 3 * VOC);
        #pragma unroll 2
        for (int k = 0; k < CHUNK; k += 4) {
            ulonglong2 n0 = *reinterpret_cast<const ulonglong2*>(wp + 4 * VOC);
            ulonglong2 n1 = *reinterpret_cast<const ulonglong2*>(wp + 5 * VOC);
            ulonglong2 n2 = *reinterpret_cast<const ulonglong2*>(wp + 6 * VOC);
            ulonglong2 n3 = *reinterpret_cast<const ulonglong2*>(wp + 7 * VOC);
            wp += 4 * VOC;
            bodyk(acc, w0, shp);
            bodyk(acc, w1, shp + 128);
            bodyk(acc, w2, shp + 256);
            bodyk(acc, w3, shp + 384);
            shp += 512;
            w0 = n0; w1 = n1; w2 = n2; w3 = n3;
        }
    }

    float4 bv = *reinterpret_cast<const float4*>(bl + r0);
    const float bias[4] = {bv.x, bv.y, bv.z, bv.w};
    const int part = blk * 2 + half;

    #pragma unroll
    for (int b = 0; b < 8; b++) {
        float v[4];
        unpack2(acc[0][b], v[0], v[1]);
        unpack2(acc[1][b], v[2], v[3]);
        #pragma unroll
        for (int i = 0; i < 4; i++) v[i] += bias[i];
        int bb = b0 + b;
        float bestv = v[0]; int besti = r0;
        #pragma unroll
        for (int i = 1; i < 4; i++)
            if (v[i] > bestv) { bestv = v[i]; besti = r0 + i; }
        #pragma unroll
        for (int s = 16; s > 0; s >>= 1) {
            float ov = __shfl_xor_sync(0xffffffffu, bestv, s);
            int   oi = __shfl_xor_sync(0xffffffffu, besti, s);
            if (ov > bestv || (ov == bestv && oi < besti)) { bestv = ov; besti = oi; }
        }
        if (lane == 0) { g_pv[part * 64 + bb] = bestv; g_pi[part * 64 + bb] = besti; }
        float* op = out + (size_t)bb * (TT * VOC) + (size_t)t * VOC + r0;
        *reinterpret_cast<float4*>(op) = make_float4(v[0], v[1], v[2], v[3]);
    }
}

// ---------------- kC: argmax finalize, word/mask/done update ----------------
__global__ __launch_bounds__(512) void kC() {
    if (g_done) return;
    __shared__ float sv[512];
    __shared__ int   si[512];
    __shared__ int   sm[64];
    int tid = threadIdx.x;
    int b = tid & 63, q = tid >> 6;                 // q in 0..7
    int s = q * 32, e = (s + 32 < NPART) ? s + 32 : NPART;
    float best = -1e30f; int bi = 0x7fffffff;
    for (int k = s; k < e; k++) {
        float v = g_pv[k * 64 + b];
        int   i = g_pi[k * 64 + b];
        if (v > best || (v == best && i < bi)) { best = v; bi = i; }
    }
    sv[q * 64 + b] = best; si[q * 64 + b] = bi;
    __syncthreads();
    if (tid < 64) {
        float bvv = sv[tid]; int bix = si[tid];
        #pragma unroll
        for (int q2 = 1; q2 < 8; q2++) {
            float v = sv[q2 * 64 + tid]; int i = si[q2 * 64 + tid];
            if (v > bvv || (v == bvv && i < bix)) { bvv = v; bix = i; }
        }
        g_word[tid] = bix;
        int m = g_mask[tid] | (bix == END_TOK);
        g_mask[tid] = m;
        sm[tid] = m;
    }
    __syncthreads();
    if (tid == 0) {
        int all = 1;
        for (int b2 = 0; b2 < 64; b2++) all &= sm[b2];
        if (all) g_done = 1;
    }
}

extern "C" void kernel_launch(void* const* d_in, const int* in_sizes, int n_in,
                              void* d_out, int out_size) {
    const float* feat = (const float*)d_in[0];
    const float* emb  = (const float*)d_in[1];
    const float* Wih  = (const float*)d_in[2];
    const float* Whh  = (const float*)d_in[3];
    const float* bih  = (const float*)d_in[4];
    const float* bhh  = (const float*)d_in[5];
    const float* Wl   = (const float*)d_in[6];
    const float* bl   = (const float*)d_in[7];
    float* out = (float*)d_out;

    static int s_attr_done = 0;
    if (!s_attr_done) {
        cudaFuncSetAttribute(kB, cudaFuncAttributeMaxDynamicSharedMemorySize,
                             CHUNK * 128 * 4);
        s_attr_done = 1;
    }

    kTransL<<<dim3(1000, 16), dim3(32, 8)>>>(Wl);
    kTransG<<<dim3(64, 32), dim3(32, 8)>>>(Wih, Whh);
    kInit<<<64, 512>>>(feat);
    for (int t = 0; t < TT; t++) {
        kGates<<<dim3(8, 16), 512>>>(emb);
        kPoint<<<64, 512>>>(bih, bhh);
        kB<<<NBLK_B, 512, CHUNK * 128 * 4>>>(bl, out, t);
        kC<<<1, 512>>>();
    }
}

// round 9
// speedup vs baseline: 1.5483x; 1.1220x over previous
#include <cuda_runtime.h>
#include <math.h>
#include <stdint.h>

typedef unsigned long long u64;

#define NB    64
#define HID   512
#define VOC   32000
#define TT    50
#define NBLK_B 250
#define NPART 250
#define NKS   16
#define START_TOK 1
#define END_TOK 2
#define CHUNK 128
#define DYN_SMEM (CHUNK * 128 * 4)

// ---------------- device scratch ----------------
__device__ float g_Wlt[HID * VOC];        // W_lin transposed [k][r]
__device__ float g_Wgt[1024 * 2048];      // gates W transposed [k][j]
__device__ float g_sv[HID * NB];          // h transposed [k][b]
__device__ float g_c[NB * HID];
__device__ float g_gp[NKS][NB * 2048];    // split-K gate partials
__device__ int   g_word[NB];
__device__ int   g_mask[NB];
__device__ int   g_done;
__device__ float g_pv[NPART * NB];
__device__ int   g_pi[NPART * NB];

// ---------------- helpers ----------------
__device__ __forceinline__ void unpack2(u64 v, float &a, float &b) {
    asm("mov.b64 {%0, %1}, %2;" : "=f"(a), "=f"(b) : "l"(v));
}
__device__ __forceinline__ void ffma2(u64 &d, u64 a, u64 b) {
    asm("fma.rn.f32x2 %0, %1, %2, %0;" : "+l"(d) : "l"(a), "l"(b));
}
__device__ __forceinline__ void stcs4(float* p, float4 v) {
    asm volatile("st.global.cs.v4.f32 [%0], {%1, %2, %3, %4};"
                 :: "l"(p), "f"(v.x), "f"(v.y), "f"(v.z), "f"(v.w) : "memory");
}

// kGates micro-step: w = 2 row-pairs (4 rows), sh -> 8 dup batch values
__device__ __forceinline__ void bodyk(u64 (&acc)[2][8], ulonglong2 w, const float* sh) {
    ulonglong2 h0 = *reinterpret_cast<const ulonglong2*>(sh);
    ulonglong2 h1 = *reinterpret_cast<const ulonglong2*>(sh + 4);
    ulonglong2 h2 = *reinterpret_cast<const ulonglong2*>(sh + 8);
    ulonglong2 h3 = *reinterpret_cast<const ulonglong2*>(sh + 12);
    ffma2(acc[0][0], w.x, h0.x); ffma2(acc[1][0], w.y, h0.x);
    ffma2(acc[0][1], w.x, h0.y); ffma2(acc[1][1], w.y, h0.y);
    ffma2(acc[0][2], w.x, h1.x); ffma2(acc[1][2], w.y, h1.x);
    ffma2(acc[0][3], w.x, h1.y); ffma2(acc[1][3], w.y, h1.y);
    ffma2(acc[0][4], w.x, h2.x); ffma2(acc[1][4], w.y, h2.x);
    ffma2(acc[0][5], w.x, h2.y); ffma2(acc[1][5], w.y, h2.y);
    ffma2(acc[0][6], w.x, h3.x); ffma2(acc[1][6], w.y, h3.x);
    ffma2(acc[0][7], w.x, h3.y); ffma2(acc[1][7], w.y, h3.y);
}

// kB micro-step: w = 2 row-pairs (4 rows), sh -> 4 dup batch values
__device__ __forceinline__ void bodyk4(u64 (&acc)[2][4], ulonglong2 w, const float* sh) {
    ulonglong2 h0 = *reinterpret_cast<const ulonglong2*>(sh);
    ulonglong2 h1 = *reinterpret_cast<const ulonglong2*>(sh + 4);
    ffma2(acc[0][0], w.x, h0.x); ffma2(acc[1][0], w.y, h0.x);
    ffma2(acc[0][1], w.x, h0.y); ffma2(acc[1][1], w.y, h0.y);
    ffma2(acc[0][2], w.x, h1.x); ffma2(acc[1][2], w.y, h1.x);
    ffma2(acc[0][3], w.x, h1.y); ffma2(acc[1][3], w.y, h1.y);
}

// ---------------- weight transposes (once per replay) ----------------
__global__ void kTransL(const float* __restrict__ Wl) {
    __shared__ float tile[32][33];
    int r0 = blockIdx.x * 32, k0 = blockIdx.y * 32;
    int tx = threadIdx.x, ty = threadIdx.y;
    #pragma unroll
    for (int i = 0; i < 4; i++)
        tile[ty + 8 * i][tx] = Wl[(size_t)(r0 + ty + 8 * i) * HID + k0 + tx];
    __syncthreads();
    #pragma unroll
    for (int i = 0; i < 4; i++)
        g_Wlt[(size_t)(k0 + ty + 8 * i) * VOC + r0 + tx] = tile[tx][ty + 8 * i];
}

__global__ void kTransG(const float* __restrict__ Wih, const float* __restrict__ Whh) {
    __shared__ float tile[32][33];
    int j0 = blockIdx.x * 32, k0 = blockIdx.y * 32;
    const float* W = (k0 < 512) ? Wih : Whh;
    int kk = (k0 < 512) ? k0 : k0 - 512;
    int tx = threadIdx.x, ty = threadIdx.y;
    #pragma unroll
    for (int i = 0; i < 4; i++)
        tile[ty + 8 * i][tx] = W[(size_t)(j0 + ty + 8 * i) * 512 + kk + tx];
    __syncthreads();
    #pragma unroll
    for (int i = 0; i < 4; i++)
        g_Wgt[(size_t)(k0 + ty + 8 * i) * 2048 + j0 + tx] = tile[tx][ty + 8 * i];
}

// ---------------- init ----------------
__global__ void kInit(const float* __restrict__ feat) {
    int gid = blockIdx.x * blockDim.x + threadIdx.x;   // 64 x 512
    int b = gid >> 9, u = gid & 511;
    g_c[b * 512 + u] = 0.f;
    g_sv[u * 64 + b] = feat[b * 512 + u];
    if (gid < NB) { g_word[gid] = START_TOK; g_mask[gid] = 0; }
    if (gid == 0)   g_done = 0;
}

// ---------------- kGates (R7 structure, unchanged) ----------------
__global__ __launch_bounds__(512) void kGates(const float* __restrict__ emb) {
    __shared__ __align__(16) float s_hd[64 * 128];
    if (g_done) return;
    const int tid = threadIdx.x, lane = tid & 31, wid = tid >> 5;
    const int ks = blockIdx.y;
    const int kb = ks * 64;
    const int r0 = blockIdx.x * 256 + (wid >> 3) * 128 + lane * 4;
    const int b0 = (wid & 7) * 8;

    if (ks < 8) {
        for (int idx = tid; idx < 64 * 16; idx += 512) {
            int k = idx >> 4, g = idx & 15;
            float4 v;
            v.x = emb[(size_t)g_word[4 * g + 0] * 512 + kb + k];
            v.y = emb[(size_t)g_word[4 * g + 1] * 512 + kb + k];
            v.z = emb[(size_t)g_word[4 * g + 2] * 512 + kb + k];
            v.w = emb[(size_t)g_word[4 * g + 3] * 512 + kb + k];
            float2* d = reinterpret_cast<float2*>(&s_hd[k * 128 + g * 8]);
            d[0] = make_float2(v.x, v.x); d[1] = make_float2(v.y, v.y);
            d[2] = make_float2(v.z, v.z); d[3] = make_float2(v.w, v.w);
        }
    } else {
        for (int idx = tid; idx < 64 * 16; idx += 512) {
            int k = idx >> 4, g = idx & 15;
            float4 v = *reinterpret_cast<const float4*>(&g_sv[(kb - 512 + k) * 64 + g * 4]);
            float2* d = reinterpret_cast<float2*>(&s_hd[k * 128 + g * 8]);
            d[0] = make_float2(v.x, v.x); d[1] = make_float2(v.y, v.y);
            d[2] = make_float2(v.z, v.z); d[3] = make_float2(v.w, v.w);
        }
    }
    __syncthreads();

    u64 acc[2][8];
    #pragma unroll
    for (int r = 0; r < 2; r++)
        #pragma unroll
        for (int b = 0; b < 8; b++) acc[r][b] = 0ull;

    const float* wp = g_Wgt + (size_t)kb * 2048 + r0;
    const float* shp = s_hd + 2 * b0;
    ulonglong2 w0 = *reinterpret_cast<const ulonglong2*>(wp);
    ulonglong2 w1 = *reinterpret_cast<const ulonglong2*>(wp + 2048);
    ulonglong2 w2 = *reinterpret_cast<const ulonglong2*>(wp + 2 * 2048);
    ulonglong2 w3 = *reinterpret_cast<const ulonglong2*>(wp + 3 * 2048);
    #pragma unroll 2
    for (int k = 0; k < 64; k += 4) {
        ulonglong2 n0 = *reinterpret_cast<const ulonglong2*>(wp + 4 * 2048);
        ulonglong2 n1 = *reinterpret_cast<const ulonglong2*>(wp + 5 * 2048);
        ulonglong2 n2 = *reinterpret_cast<const ulonglong2*>(wp + 6 * 2048);
        ulonglong2 n3 = *reinterpret_cast<const ulonglong2*>(wp + 7 * 2048);
        wp += 4 * 2048;
        bodyk(acc, w0, shp);
        bodyk(acc, w1, shp + 128);
        bodyk(acc, w2, shp + 256);
        bodyk(acc, w3, shp + 384);
        shp += 512;
        w0 = n0; w1 = n1; w2 = n2; w3 = n3;
    }

    #pragma unroll
    for (int b = 0; b < 8; b++) {
        float v0, v1, v2, v3;
        unpack2(acc[0][b], v0, v1);
        unpack2(acc[1][b], v2, v3);
        *reinterpret_cast<float4*>(&g_gp[ks][(b0 + b) * 2048 + r0]) =
            make_float4(v0, v1, v2, v3);
    }
}

// ---------------- kPoint ----------------
__global__ void kPoint(const float* __restrict__ bih, const float* __restrict__ bhh) {
    if (g_done) return;
    int gid = blockIdx.x * blockDim.x + threadIdx.x;
    int b = gid >> 9, u = gid & 511;
    float gate[4];
    #pragma unroll
    for (int q = 0; q < 4; q++) {
        int j = u + 512 * q;
        float s = bih[j] + bhh[j];
        #pragma unroll
        for (int ks = 0; ks < NKS; ks++) s += g_gp[ks][b * 2048 + j];
        gate[q] = s;
    }
    float ii = 1.f / (1.f + expf(-gate[0]));
    float ff = 1.f / (1.f + expf(-gate[1]));
    float gg = tanhf(gate[2]);
    float oo = 1.f / (1.f + expf(-gate[3]));
    float c = ff * g_c[gid] + ii * gg;
    g_c[gid] = c;
    g_sv[u * 64 + b] = oo * tanhf(c);
}

// ---------------- kB: logits GEMM, 2 blocks/SM ----------------
// grid 250 x 512 thr: block = 128 vocab rows x 64 batches.
// warp: all 128 rows (lane*4), batches wid*4 .. wid*4+3.
__global__ __launch_bounds__(512, 2) void kB(const float* __restrict__ bl,
                                             float* __restrict__ out, int t) {
    extern __shared__ float s_hd[];          // [CHUNK][128] duplicated h
    const int tid = threadIdx.x, lane = tid & 31, wid = tid >> 5;
    const int blk = blockIdx.x;
    const int r0 = blk * 128 + lane * 4;
    const int b0 = wid * 4;

    if (g_done) {
        for (int idx = tid; idx < 128 * 64; idx += 512) {
            int b = idx >> 7, r = idx & 127;
            out[(size_t)b * (TT * VOC) + (size_t)t * VOC + blk * 128 + r] = 0.f;
        }
        return;
    }

    u64 acc[2][4];
    #pragma unroll
    for (int r = 0; r < 2; r++)
        #pragma unroll
        for (int b = 0; b < 4; b++) acc[r][b] = 0ull;

    const float* wbase = g_Wlt + r0;

    for (int ch = 0; ch < 4; ch++) {
        if (ch) __syncthreads();
        for (int idx = tid; idx < CHUNK * 16; idx += 512) {
            int k = idx >> 4, g = idx & 15;
            float4 v = *reinterpret_cast<const float4*>(&g_sv[(ch * CHUNK + k) * 64 + g * 4]);
            float2* d = reinterpret_cast<float2*>(&s_hd[k * 128 + g * 8]);
            d[0] = make_float2(v.x, v.x); d[1] = make_float2(v.y, v.y);
            d[2] = make_float2(v.z, v.z); d[3] = make_float2(v.w, v.w);
        }
        __syncthreads();

        const float* wp = wbase + (size_t)ch * CHUNK * VOC;
        const float* shp = s_hd + 2 * b0;
        ulonglong2 w0 = *reinterpret_cast<const ulonglong2*>(wp);
        ulonglong2 w1 = *reinterpret_cast<const ulonglong2*>(wp + VOC);
        ulonglong2 w2 = *reinterpret_cast<const ulonglong2*>(wp + 2 * VOC);
        ulonglong2 w3 = *reinterpret_cast<const ulonglong2*>(wp + 3 * VOC);
        #pragma unroll 2
        for (int k = 0; k < CHUNK; k += 4) {
            ulonglong2 n0 = *reinterpret_cast<const ulonglong2*>(wp + 4 * VOC);
            ulonglong2 n1 = *reinterpret_cast<const ulonglong2*>(wp + 5 * VOC);
            ulonglong2 n2 = *reinterpret_cast<const ulonglong2*>(wp + 6 * VOC);
            ulonglong2 n3 = *reinterpret_cast<const ulonglong2*>(wp + 7 * VOC);
            wp += 4 * VOC;
            bodyk4(acc, w0, shp);
            bodyk4(acc, w1, shp + 128);
            bodyk4(acc, w2, shp + 256);
            bodyk4(acc, w3, shp + 384);
            shp += 512;
            w0 = n0; w1 = n1; w2 = n2; w3 = n3;
        }
    }

    float4 bv = *reinterpret_cast<const float4*>(bl + r0);
    const float bias[4] = {bv.x, bv.y, bv.z, bv.w};

    #pragma unroll
    for (int b = 0; b < 4; b++) {
        float v[4];
        unpack2(acc[0][b], v[0], v[1]);
        unpack2(acc[1][b], v[2], v[3]);
        #pragma unroll
        for (int i = 0; i < 4; i++) v[i] += bias[i];
        int bb = b0 + b;
        float bestv = v[0]; int besti = r0;
        #pragma unroll
        for (int i = 1; i < 4; i++)
            if (v[i] > bestv) { bestv = v[i]; besti = r0 + i; }
        #pragma unroll
        for (int s = 16; s > 0; s >>= 1) {
            float ov = __shfl_xor_sync(0xffffffffu, bestv, s);
            int   oi = __shfl_xor_sync(0xffffffffu, besti, s);
            if (ov > bestv || (ov == bestv && oi < besti)) { bestv = ov; besti = oi; }
        }
        if (lane == 0) { g_pv[blk * 64 + bb] = bestv; g_pi[blk * 64 + bb] = besti; }
        stcs4(out + (size_t)bb * (TT * VOC) + (size_t)t * VOC + r0,
              make_float4(v[0], v[1], v[2], v[3]));
    }
}

// ---------------- kC: argmax finalize ----------------
__global__ __launch_bounds__(512) void kC() {
    if (g_done) return;
    __shared__ float sv[512];
    __shared__ int   si[512];
    __shared__ int   sm[64];
    int tid = threadIdx.x;
    int b = tid & 63, q = tid >> 6;                 // q 0..7
    int s = q * 32, e = (s + 32 < NPART) ? s + 32 : NPART;
    float best = -1e30f; int bi = 0x7fffffff;
    for (int k = s; k < e; k++) {
        float v = g_pv[k * 64 + b];
        int   i = g_pi[k * 64 + b];
        if (v > best || (v == best && i < bi)) { best = v; bi = i; }
    }
    sv[q * 64 + b] = best; si[q * 64 + b] = bi;
    __syncthreads();
    if (tid < 64) {
        float bvv = sv[tid]; int bix = si[tid];
        #pragma unroll
        for (int q2 = 1; q2 < 8; q2++) {
            float v = sv[q2 * 64 + tid]; int i = si[q2 * 64 + tid];
            if (v > bvv || (v == bvv && i < bix)) { bvv = v; bix = i; }
        }
        g_word[tid] = bix;
        int m = g_mask[tid] | (bix == END_TOK);
        g_mask[tid] = m;
        sm[tid] = m;
    }
    __syncthreads();
    if (tid == 0) {
        int all = 1;
        for (int b2 = 0; b2 < 64; b2++) all &= sm[b2];
        if (all) g_done = 1;
    }
}

extern "C" void kernel_launch(void* const* d_in, const int* in_sizes, int n_in,
                              void* d_out, int out_size) {
    const float* feat = (const float*)d_in[0];
    const float* emb  = (const float*)d_in[1];
    const float* Wih  = (const float*)d_in[2];
    const float* Whh  = (const float*)d_in[3];
    const float* bih  = (const float*)d_in[4];
    const float* bhh  = (const float*)d_in[5];
    const float* Wl   = (const float*)d_in[6];
    const float* bl   = (const float*)d_in[7];
    float* out = (float*)d_out;

    cudaFuncSetAttribute(kB, cudaFuncAttributeMaxDynamicSharedMemorySize, DYN_SMEM);

    kTransL<<<dim3(1000, 16), dim3(32, 8)>>>(Wl);
    kTransG<<<dim3(64, 32), dim3(32, 8)>>>(Wih, Whh);
    kInit<<<64, 512>>>(feat);
    for (int t = 0; t < TT; t++) {
        kGates<<<dim3(8, 16), 512>>>(emb);
        kPoint<<<64, 512>>>(bih, bhh);
        kB<<<NBLK_B, 512, DYN_SMEM>>>(bl, out, t);
        kC<<<1, 512>>>();
    }
}

// round 11
// speedup vs baseline: 1.7605x; 1.1370x over previous
#include <cuda_runtime.h>
#include <math.h>
#include <stdint.h>

typedef unsigned long long u64;

#define NB    64
#define HID   512
#define VOC   32000
#define TT    50
#define NBLK_B 250
#define NPART 250
#define NKS   16
#define START_TOK 1
#define END_TOK 2

// kBmma smem: ws_hi[128][72] | ws_lo[128][72] | hs_hi[64][72] | hs_lo[64][72]
#define WS_F   (128 * 72)
#define HS_F   (64 * 72)
#define MMA_SMEM ((2 * WS_F + 2 * HS_F) * 4)

// ---------------- device scratch ----------------
__device__ float g_Wh[VOC * HID];         // W_lin tf32-hi [r][k]
__device__ float g_Wlo[VOC * HID];        // W_lin tf32-lo [r][k]
__device__ float g_Wgt[1024 * 2048];      // gates W transposed [k][j]
__device__ float g_sv[HID * NB];          // h transposed [k][b] (kGates)
__device__ float g_aht[HID * NB];         // h tf32-hi transposed [k][b]
__device__ float g_alt[HID * NB];         // h tf32-lo transposed [k][b]
__device__ float g_c[NB * HID];
__device__ float g_gp[NKS][NB * 2048];
__device__ int   g_word[NB];
__device__ int   g_mask[NB];
__device__ int   g_done;
__device__ float g_pv[NPART * NB];
__device__ int   g_pi[NPART * NB];

// ---------------- helpers ----------------
__device__ __forceinline__ void unpack2(u64 v, float &a, float &b) {
    asm("mov.b64 {%0, %1}, %2;" : "=f"(a), "=f"(b) : "l"(v));
}
__device__ __forceinline__ void ffma2(u64 &d, u64 a, u64 b) {
    asm("fma.rn.f32x2 %0, %1, %2, %0;" : "+l"(d) : "l"(a), "l"(b));
}
__device__ __forceinline__ void stcs4(float* p, float4 v) {
    asm volatile("st.global.cs.v4.f32 [%0], {%1, %2, %3, %4};"
                 :: "l"(p), "f"(v.x), "f"(v.y), "f"(v.z), "f"(v.w) : "memory");
}
// tf32 destination must be a .b32 register in PTX
__device__ __forceinline__ void tf32split(float f, float &hi, float &lo) {
    uint32_t hb, lb;
    asm("cvt.rna.tf32.f32 %0, %1;" : "=r"(hb) : "f"(f));
    hi = __uint_as_float(hb);
    float r = f - hi;
    asm("cvt.rna.tf32.f32 %0, %1;" : "=r"(lb) : "f"(r));
    lo = __uint_as_float(lb);
}
__device__ __forceinline__ void mma8(float (&d)[4], const uint32_t (&a)[4],
                                     const uint32_t (&b)[2]) {
    asm("mma.sync.aligned.m16n8k8.row.col.f32.tf32.tf32.f32 "
        "{%0,%1,%2,%3}, {%4,%5,%6,%7}, {%8,%9}, {%0,%1,%2,%3};"
        : "+f"(d[0]), "+f"(d[1]), "+f"(d[2]), "+f"(d[3])
        : "r"(a[0]), "r"(a[1]), "r"(a[2]), "r"(a[3]), "r"(b[0]), "r"(b[1]));
}
// kGates micro-step (R9)
__device__ __forceinline__ void bodyk(u64 (&acc)[2][8], ulonglong2 w, const float* sh) {
    ulonglong2 h0 = *reinterpret_cast<const ulonglong2*>(sh);
    ulonglong2 h1 = *reinterpret_cast<const ulonglong2*>(sh + 4);
    ulonglong2 h2 = *reinterpret_cast<const ulonglong2*>(sh + 8);
    ulonglong2 h3 = *reinterpret_cast<const ulonglong2*>(sh + 12);
    ffma2(acc[0][0], w.x, h0.x); ffma2(acc[1][0], w.y, h0.x);
    ffma2(acc[0][1], w.x, h0.y); ffma2(acc[1][1], w.y, h0.y);
    ffma2(acc[0][2], w.x, h1.x); ffma2(acc[1][2], w.y, h1.x);
    ffma2(acc[0][3], w.x, h1.y); ffma2(acc[1][3], w.y, h1.y);
    ffma2(acc[0][4], w.x, h2.x); ffma2(acc[1][4], w.y, h2.x);
    ffma2(acc[0][5], w.x, h2.y); ffma2(acc[1][5], w.y, h2.y);
    ffma2(acc[0][6], w.x, h3.x); ffma2(acc[1][6], w.y, h3.x);
    ffma2(acc[0][7], w.x, h3.y); ffma2(acc[1][7], w.y, h3.y);
}

// ---------------- once-per-replay transforms ----------------
__global__ void kSplitW(const float* __restrict__ Wl) {
    int i = blockIdx.x * 256 + threadIdx.x;
    float hi, lo;
    tf32split(Wl[i], hi, lo);
    g_Wh[i] = hi; g_Wlo[i] = lo;
}

__global__ void kTransG(const float* __restrict__ Wih, const float* __restrict__ Whh) {
    __shared__ float tile[32][33];
    int j0 = blockIdx.x * 32, k0 = blockIdx.y * 32;
    const float* W = (k0 < 512) ? Wih : Whh;
    int kk = (k0 < 512) ? k0 : k0 - 512;
    int tx = threadIdx.x, ty = threadIdx.y;
    #pragma unroll
    for (int i = 0; i < 4; i++)
        tile[ty + 8 * i][tx] = W[(size_t)(j0 + ty + 8 * i) * 512 + kk + tx];
    __syncthreads();
    #pragma unroll
    for (int i = 0; i < 4; i++)
        g_Wgt[(size_t)(k0 + ty + 8 * i) * 2048 + j0 + tx] = tile[tx][ty + 8 * i];
}

__global__ void kInit(const float* __restrict__ feat) {
    int gid = blockIdx.x * blockDim.x + threadIdx.x;   // 64 x 512
    int b = gid >> 9, u = gid & 511;
    float f = feat[b * 512 + u];
    g_c[b * 512 + u] = 0.f;
    g_sv[u * 64 + b] = f;
    float hi, lo; tf32split(f, hi, lo);
    g_aht[u * 64 + b] = hi; g_alt[u * 64 + b] = lo;
    if (gid < NB) { g_word[gid] = START_TOK; g_mask[gid] = 0; }
    if (gid == 0)   g_done = 0;
}

// ---------------- kGates (R9, unchanged) ----------------
__global__ __launch_bounds__(512) void kGates(const float* __restrict__ emb) {
    __shared__ __align__(16) float s_hd[64 * 128];
    if (g_done) return;
    const int tid = threadIdx.x, lane = tid & 31, wid = tid >> 5;
    const int ks = blockIdx.y;
    const int kb = ks * 64;
    const int r0 = blockIdx.x * 256 + (wid >> 3) * 128 + lane * 4;
    const int b0 = (wid & 7) * 8;

    if (ks < 8) {
        for (int idx = tid; idx < 64 * 16; idx += 512) {
            int k = idx >> 4, g = idx & 15;
            float4 v;
            v.x = emb[(size_t)g_word[4 * g + 0] * 512 + kb + k];
            v.y = emb[(size_t)g_word[4 * g + 1] * 512 + kb + k];
            v.z = emb[(size_t)g_word[4 * g + 2] * 512 + kb + k];
            v.w = emb[(size_t)g_word[4 * g + 3] * 512 + kb + k];
            float2* d = reinterpret_cast<float2*>(&s_hd[k * 128 + g * 8]);
            d[0] = make_float2(v.x, v.x); d[1] = make_float2(v.y, v.y);
            d[2] = make_float2(v.z, v.z); d[3] = make_float2(v.w, v.w);
        }
    } else {
        for (int idx = tid; idx < 64 * 16; idx += 512) {
            int k = idx >> 4, g = idx & 15;
            float4 v = *reinterpret_cast<const float4*>(&g_sv[(kb - 512 + k) * 64 + g * 4]);
            float2* d = reinterpret_cast<float2*>(&s_hd[k * 128 + g * 8]);
            d[0] = make_float2(v.x, v.x); d[1] = make_float2(v.y, v.y);
            d[2] = make_float2(v.z, v.z); d[3] = make_float2(v.w, v.w);
        }
    }
    __syncthreads();

    u64 acc[2][8];
    #pragma unroll
    for (int r = 0; r < 2; r++)
        #pragma unroll
        for (int b = 0; b < 8; b++) acc[r][b] = 0ull;

    const float* wp = g_Wgt + (size_t)kb * 2048 + r0;
    const float* shp = s_hd + 2 * b0;
    ulonglong2 w0 = *reinterpret_cast<const ulonglong2*>(wp);
    ulonglong2 w1 = *reinterpret_cast<const ulonglong2*>(wp + 2048);
    ulonglong2 w2 = *reinterpret_cast<const ulonglong2*>(wp + 2 * 2048);
    ulonglong2 w3 = *reinterpret_cast<const ulonglong2*>(wp + 3 * 2048);
    #pragma unroll 2
    for (int k = 0; k < 64; k += 4) {
        ulonglong2 n0 = *reinterpret_cast<const ulonglong2*>(wp + 4 * 2048);
        ulonglong2 n1 = *reinterpret_cast<const ulonglong2*>(wp + 5 * 2048);
        ulonglong2 n2 = *reinterpret_cast<const ulonglong2*>(wp + 6 * 2048);
        ulonglong2 n3 = *reinterpret_cast<const ulonglong2*>(wp + 7 * 2048);
        wp += 4 * 2048;
        bodyk(acc, w0, shp);
        bodyk(acc, w1, shp + 128);
        bodyk(acc, w2, shp + 256);
        bodyk(acc, w3, shp + 384);
        shp += 512;
        w0 = n0; w1 = n1; w2 = n2; w3 = n3;
    }

    #pragma unroll
    for (int b = 0; b < 8; b++) {
        float v0, v1, v2, v3;
        unpack2(acc[0][b], v0, v1);
        unpack2(acc[1][b], v2, v3);
        *reinterpret_cast<float4*>(&g_gp[ks][(b0 + b) * 2048 + r0]) =
            make_float4(v0, v1, v2, v3);
    }
}

// ---------------- kPoint: + tf32 splits of h (transposed) ----------------
__global__ void kPoint(const float* __restrict__ bih, const float* __restrict__ bhh) {
    if (g_done) return;
    int gid = blockIdx.x * blockDim.x + threadIdx.x;
    int b = gid >> 9, u = gid & 511;
    float gate[4];
    #pragma unroll
    for (int q = 0; q < 4; q++) {
        int j = u + 512 * q;
        float s = bih[j] + bhh[j];
        #pragma unroll
        for (int ks = 0; ks < NKS; ks++) s += g_gp[ks][b * 2048 + j];
        gate[q] = s;
    }
    float ii = 1.f / (1.f + expf(-gate[0]));
    float ff = 1.f / (1.f + expf(-gate[1]));
    float gg = tanhf(gate[2]);
    float oo = 1.f / (1.f + expf(-gate[3]));
    float c = ff * g_c[gid] + ii * gg;
    g_c[gid] = c;
    float h = oo * tanhf(c);
    g_sv[u * 64 + b] = h;
    float hi, lo; tf32split(h, hi, lo);
    g_aht[u * 64 + b] = hi; g_alt[u * 64 + b] = lo;
}

// ---------------- kBmma: mma.sync tf32-3x logits GEMM ----------------
// grid 250 x 256 thr (8 warps 4m x 2n): tile M=128 vocab x N=64 batch, K=512.
__global__ __launch_bounds__(256, 2) void kBmma(const float* __restrict__ bl,
                                                float* __restrict__ out, int t) {
    extern __shared__ __align__(16) float sm[];
    float* ws_hi = sm;
    float* ws_lo = sm + WS_F;
    float* hs_hi = sm + 2 * WS_F;
    float* hs_lo = sm + 2 * WS_F + HS_F;
    const int tid = threadIdx.x, lane = tid & 31, wid = tid >> 5;
    const int blk = blockIdx.x;
    const int r0 = blk * 128;

    if (g_done) {
        for (int idx = tid; idx < 128 * 64; idx += 256) {
            int b = idx >> 7, r = idx & 127;
            out[(size_t)b * (TT * VOC) + (size_t)t * VOC + r0 + r] = 0.f;
        }
        return;
    }

    const int wm = wid & 3, wn = wid >> 2;
    const int rA = lane >> 2, cA = lane & 3;

    float d[2][4][4];
    #pragma unroll
    for (int mt = 0; mt < 2; mt++)
        #pragma unroll
        for (int nt = 0; nt < 4; nt++)
            #pragma unroll
            for (int j = 0; j < 4; j++) d[mt][nt][j] = 0.f;

    for (int ch = 0; ch < 8; ch++) {
        if (ch) __syncthreads();
        const int kc0 = ch * 64;
        // stage W hi/lo: 128 rows x 64 k
        for (int i = tid; i < 4096; i += 256) {
            int tile = i >> 11, j = i & 2047, row = j >> 4, c4 = j & 15;
            const float* src = (tile ? g_Wlo : g_Wh)
                             + (size_t)(r0 + row) * 512 + kc0 + c4 * 4;
            float* dst = (tile ? ws_lo : ws_hi) + row * 72 + c4 * 4;
            *reinterpret_cast<float4*>(dst) = *reinterpret_cast<const float4*>(src);
        }
        // stage h hi/lo (already transposed [k][b]): 64 k x 64 b
        for (int i = tid; i < 2048; i += 256) {
            int tile = i >> 10, j = i & 1023, k = j >> 4, c4 = j & 15;
            const float* src = (tile ? g_alt : g_aht) + (kc0 + k) * 64 + c4 * 4;
            float* dst = (tile ? hs_lo : hs_hi) + k * 72 + c4 * 4;
            *reinterpret_cast<float4*>(dst) = *reinterpret_cast<const float4*>(src);
        }
        __syncthreads();

        #pragma unroll
        for (int k8 = 0; k8 < 8; k8++) {
            const int kb = k8 * 8;
            uint32_t ahi[2][4], alo[2][4], bhi[4][2], blo[4][2];
            #pragma unroll
            for (int mt = 0; mt < 2; mt++) {
                int base = (wm * 32 + mt * 16) * 72;
                #pragma unroll
                for (int j = 0; j < 4; j++) {
                    int off = base + (rA + (j & 1) * 8) * 72 + kb + cA + (j >> 1) * 4;
                    ahi[mt][j] = __float_as_uint(ws_hi[off]);
                    alo[mt][j] = __float_as_uint(ws_lo[off]);
                }
            }
            #pragma unroll
            for (int nt = 0; nt < 4; nt++) {
                int nn = wn * 32 + nt * 8 + rA;
                #pragma unroll
                for (int j = 0; j < 2; j++) {
                    int off = (kb + cA + j * 4) * 72 + nn;
                    bhi[nt][j] = __float_as_uint(hs_hi[off]);
                    blo[nt][j] = __float_as_uint(hs_lo[off]);
                }
            }
            #pragma unroll
            for (int mt = 0; mt < 2; mt++)
                #pragma unroll
                for (int nt = 0; nt < 4; nt++) {
                    mma8(d[mt][nt], ahi[mt], bhi[nt]);
                    mma8(d[mt][nt], ahi[mt], blo[nt]);
                    mma8(d[mt][nt], alo[mt], bhi[nt]);
                }
        }
    }
    __syncthreads();

    // stage D to smem st[128][72]
    float* st = sm;
    #pragma unroll
    for (int mt = 0; mt < 2; mt++)
        #pragma unroll
        for (int nt = 0; nt < 4; nt++)
            #pragma unroll
            for (int j = 0; j < 4; j++) {
                int m = wm * 32 + mt * 16 + rA + (j >> 1) * 8;
                int n = wn * 32 + nt * 8 + 2 * cA + (j & 1);
                st[m * 72 + n] = d[mt][nt][j];
            }
    __syncthreads();

    // bias + coalesced store + per-quarter argmax (tid -> batch b, quarter q)
    float* cv = sm + 128 * 72;
    int*   ci = reinterpret_cast<int*>(cv + 256);
    {
        int b = tid >> 2, q = tid & 3;
        float best = -1e30f; int bi = 0;
        float* op = out + (size_t)b * (TT * VOC) + (size_t)t * VOC + r0 + q * 32;
        #pragma unroll
        for (int g = 0; g < 8; g++) {
            int rb = q * 32 + g * 4;
            float4 v;
            v.x = st[(rb + 0) * 72 + b] + bl[r0 + rb + 0];
            v.y = st[(rb + 1) * 72 + b] + bl[r0 + rb + 1];
            v.z = st[(rb + 2) * 72 + b] + bl[r0 + rb + 2];
            v.w = st[(rb + 3) * 72 + b] + bl[r0 + rb + 3];
            if (v.x > best) { best = v.x; bi = r0 + rb; }
            if (v.y > best) { best = v.y; bi = r0 + rb + 1; }
            if (v.z > best) { best = v.z; bi = r0 + rb + 2; }
            if (v.w > best) { best = v.w; bi = r0 + rb + 3; }
            stcs4(op + g * 4, v);
        }
        cv[tid] = best; ci[tid] = bi;
    }
    __syncthreads();
    if ((tid & 3) == 0) {
        int b = tid >> 2;
        float best = cv[tid]; int bi = ci[tid];
        #pragma unroll
        for (int q = 1; q < 4; q++) {
            float v = cv[tid + q]; int i = ci[tid + q];
            if (v > best || (v == best && i < bi)) { best = v; bi = i; }
        }
        g_pv[blk * 64 + b] = best; g_pi[blk * 64 + b] = bi;
    }
}

// ---------------- kC (R9, NPART=250) ----------------
__global__ __launch_bounds__(512) void kC() {
    if (g_done) return;
    __shared__ float sv[512];
    __shared__ int   si[512];
    __shared__ int   sm2[64];
    int tid = threadIdx.x;
    int b = tid & 63, q = tid >> 6;
    int s = q * 32, e = (s + 32 < NPART) ? s + 32 : NPART;
    float best = -1e30f; int bi = 0x7fffffff;
    for (int k = s; k < e; k++) {
        float v = g_pv[k * 64 + b];
        int   i = g_pi[k * 64 + b];
        if (v > best || (v == best && i < bi)) { best = v; bi = i; }
    }
    sv[q * 64 + b] = best; si[q * 64 + b] = bi;
    __syncthreads();
    if (tid < 64) {
        float bvv = sv[tid]; int bix = si[tid];
        #pragma unroll
        for (int q2 = 1; q2 < 8; q2++) {
            float v = sv[q2 * 64 + tid]; int i = si[q2 * 64 + tid];
            if (v > bvv || (v == bvv && i < bix)) { bvv = v; bix = i; }
        }
        g_word[tid] = bix;
        int m = g_mask[tid] | (bix == END_TOK);
        g_mask[tid] = m;
        sm2[tid] = m;
    }
    __syncthreads();
    if (tid == 0) {
        int all = 1;
        for (int b2 = 0; b2 < 64; b2++) all &= sm2[b2];
        if (all) g_done = 1;
    }
}

extern "C" void kernel_launch(void* const* d_in, const int* in_sizes, int n_in,
                              void* d_out, int out_size) {
    const float* feat = (const float*)d_in[0];
    const float* emb  = (const float*)d_in[1];
    const float* Wih  = (const float*)d_in[2];
    const float* Whh  = (const float*)d_in[3];
    const float* Wl   = (const float*)d_in[6];
    const float* bih  = (const float*)d_in[4];
    const float* bhh  = (const float*)d_in[5];
    const float* bl   = (const float*)d_in[7];
    float* out = (float*)d_out;

    cudaFuncSetAttribute(kBmma, cudaFuncAttributeMaxDynamicSharedMemorySize, MMA_SMEM);

    kSplitW<<<VOC * HID / 256, 256>>>(Wl);
    kTransG<<<dim3(64, 32), dim3(32, 8)>>>(Wih, Whh);
    kInit<<<64, 512>>>(feat);
    for (int t = 0; t < TT; t++) {
        kGates<<<dim3(8, 16), 512>>>(emb);
        kPoint<<<64, 512>>>(bih, bhh);
        kBmma<<<NBLK_B, 256, MMA_SMEM>>>(bl, out, t);
        kC<<<1, 512>>>();
    }
}

// round 14
// speedup vs baseline: 2.0044x; 1.1385x over previous
#include <cuda_runtime.h>
#include <math.h>
#include <stdint.h>

typedef unsigned long long u64;

#define NB    64
#define HID   512
#define VOC   32000
#define TT    50
#define NBLK_B 250
#define NPART 250
#define NKS   8
#define START_TOK 1
#define END_TOK 2

// ---- kBmma smem (floats): 2 buffers of [Whi 128x40 | Wlo 128x40 | hhi 32x72 | hlo 32x72]
#define WS_TILE 5120
#define HS_TILE 2304
#define BUF_FLOATS (2 * WS_TILE + 2 * HS_TILE)      // 14848
#define BMMA_SMEM (2 * BUF_FLOATS * 4)              // 118784 bytes
// ---- kGatesM smem (floats): Whi 128x72 | Wlo 128x72 | hhi 64x72 | hlo 64x72
#define GW_TILE 9216
#define GH_TILE 4608
#define GATES_SMEM ((2 * GW_TILE + 2 * GH_TILE) * 4) // 110592 bytes

// ---------------- device scratch ----------------
__device__ float g_Wh[VOC * HID];          // W_lin tf32-hi [r][k]
__device__ float g_Wlo[VOC * HID];         // W_lin tf32-lo [r][k]
__device__ float g_Wgh[2048 * 1024];       // gates W combined hi [j][k]
__device__ float g_Wgl[2048 * 1024];       // gates W combined lo
__device__ float g_aht[HID * NB];          // h tf32-hi transposed [k][b]
__device__ float g_alt[HID * NB];          // h tf32-lo transposed [k][b]
__device__ float g_xht[HID * NB];          // x=emb[word] tf32-hi transposed [k][b]
__device__ float g_xlt[HID * NB];          // x tf32-lo
__device__ float g_c[NB * HID];
__device__ float g_gp[NKS][NB * 2048];     // split-K gate partials
__device__ int   g_word[NB];
__device__ int   g_mask[NB];
__device__ int   g_done;
__device__ float g_pv[NPART * NB];
__device__ int   g_pi[NPART * NB];

// ---------------- helpers ----------------
__device__ __forceinline__ void stcs4(float* p, float4 v) {
    asm volatile("st.global.cs.v4.f32 [%0], {%1, %2, %3, %4};"
                 :: "l"(p), "f"(v.x), "f"(v.y), "f"(v.z), "f"(v.w) : "memory");
}
__device__ __forceinline__ void tf32split(float f, float &hi, float &lo) {
    uint32_t hb, lb;
    asm("cvt.rna.tf32.f32 %0, %1;" : "=r"(hb) : "f"(f));
    hi = __uint_as_float(hb);
    float r = f - hi;
    asm("cvt.rna.tf32.f32 %0, %1;" : "=r"(lb) : "f"(r));
    lo = __uint_as_float(lb);
}
__device__ __forceinline__ void mma8(float (&d)[4], const uint32_t (&a)[4],
                                     const uint32_t (&b)[2]) {
    asm("mma.sync.aligned.m16n8k8.row.col.f32.tf32.tf32.f32 "
        "{%0,%1,%2,%3}, {%4,%5,%6,%7}, {%8,%9}, {%0,%1,%2,%3};"
        : "+f"(d[0]), "+f"(d[1]), "+f"(d[2]), "+f"(d[3])
        : "r"(a[0]), "r"(a[1]), "r"(a[2]), "r"(a[3]), "r"(b[0]), "r"(b[1]));
}
__device__ __forceinline__ uint32_t smem_u32(const void* p) {
    uint32_t a;
    asm("{ .reg .u64 t; cvta.to.shared.u64 t, %1; cvt.u32.u64 %0, t; }" : "=r"(a) : "l"(p));
    return a;
}
__device__ __forceinline__ void cpa16(uint32_t saddr, const float* g) {
    asm volatile("cp.async.ca.shared.global [%0], [%1], 16;" :: "r"(saddr), "l"(g));
}

// ---------------- once-per-replay transforms ----------------
__global__ void kSplitW(const float* __restrict__ Wl) {
    int i = blockIdx.x * 256 + threadIdx.x;
    float hi, lo;
    tf32split(Wl[i], hi, lo);
    g_Wh[i] = hi; g_Wlo[i] = lo;
}
__global__ void kSplitG(const float* __restrict__ Wih, const float* __restrict__ Whh) {
    int i = blockIdx.x * 256 + threadIdx.x;
    int j = i >> 10, k = i & 1023;
    float v = (k < 512) ? Wih[j * 512 + k] : Whh[j * 512 + k - 512];
    float hi, lo;
    tf32split(v, hi, lo);
    g_Wgh[i] = hi; g_Wgl[i] = lo;
}
__global__ void kInit(const float* __restrict__ feat) {
    int gid = blockIdx.x * blockDim.x + threadIdx.x;   // 64 x 512
    int b = gid >> 9, u = gid & 511;
    float f = feat[b * 512 + u];
    g_c[b * 512 + u] = 0.f;
    float hi, lo; tf32split(f, hi, lo);
    g_aht[u * 64 + b] = hi; g_alt[u * 64 + b] = lo;
    if (gid < NB) { g_word[gid] = START_TOK; g_mask[gid] = 0; }
    if (gid == 0)   g_done = 0;
}

// ---------------- kEmb: gather emb[word] + tf32 split, transposed ----------------
__global__ void kEmb(const float* __restrict__ emb) {
    if (g_done) return;
    int b = blockIdx.x, u = threadIdx.x;      // 64 blocks x 512
    float v = emb[(size_t)g_word[b] * 512 + u];
    float hi, lo; tf32split(v, hi, lo);
    g_xht[u * 64 + b] = hi; g_xlt[u * 64 + b] = lo;
}

// ---------------- kGatesM: gates GEMM via mma (tf32-3x) ----------------
// grid (16, 8): x -> 128 gate rows, y = 128-k slice; 256 thr (8 warps 4m x 2n).
__global__ __launch_bounds__(256) void kGatesM() {
    extern __shared__ __align__(16) float sm[];
    if (g_done) return;
    float* ws_hi = sm;
    float* ws_lo = sm + GW_TILE;
    float* hs_hi = sm + 2 * GW_TILE;
    float* hs_lo = sm + 2 * GW_TILE + GH_TILE;
    const int tid = threadIdx.x, lane = tid & 31, wid = tid >> 5;
    const int r0 = blockIdx.x * 128;
    const int ky = blockIdx.y;
    const int kbase = ky * 128;
    const int wm = wid & 3, wn = wid >> 2;
    const int rA = lane >> 2, cA = lane & 3;

    const float* hsrc_hi = (ky < 4) ? (g_xht + kbase * 64) : (g_aht + (kbase - 512) * 64);
    const float* hsrc_lo = (ky < 4) ? (g_xlt + kbase * 64) : (g_alt + (kbase - 512) * 64);

    float d[2][4][4];
    #pragma unroll
    for (int mt = 0; mt < 2; mt++)
        #pragma unroll
        for (int nt = 0; nt < 4; nt++)
            #pragma unroll
            for (int j = 0; j < 4; j++) d[mt][nt][j] = 0.f;

    for (int ch = 0; ch < 2; ch++) {
        if (ch) __syncthreads();
        const int kc0 = ch * 64;
        for (int i = tid; i < 4096; i += 256) {     // W: 2 tiles x 128 rows x 16 f4
            int tile = i >> 11, j = i & 2047, row = j >> 4, c4 = j & 15;
            const float* src = (tile ? g_Wgl : g_Wgh)
                             + (size_t)(r0 + row) * 1024 + kbase + kc0 + c4 * 4;
            float* dst = (tile ? ws_lo : ws_hi) + row * 72 + c4 * 4;
            *reinterpret_cast<float4*>(dst) = *reinterpret_cast<const float4*>(src);
        }
        for (int i = tid; i < 2048; i += 256) {     // h/x: 2 tiles x 64 k x 16 f4
            int tile = i >> 10, j = i & 1023, k = j >> 4, c4 = j & 15;
            const float* src = (tile ? hsrc_lo : hsrc_hi) + (kc0 + k) * 64 + c4 * 4;
            float* dst = (tile ? hs_lo : hs_hi) + k * 72 + c4 * 4;
            *reinterpret_cast<float4*>(dst) = *reinterpret_cast<const float4*>(src);
        }
        __syncthreads();

        #pragma unroll
        for (int k8 = 0; k8 < 8; k8++) {
            const int kb = k8 * 8;
            uint32_t ahi[2][4], alo[2][4], bhi[4][2], blo[4][2];
            #pragma unroll
            for (int mt = 0; mt < 2; mt++) {
                int base = (wm * 32 + mt * 16) * 72;
                #pragma unroll
                for (int j = 0; j < 4; j++) {
                    int off = base + (rA + (j & 1) * 8) * 72 + kb + cA + (j >> 1) * 4;
                    ahi[mt][j] = __float_as_uint(ws_hi[off]);
                    alo[mt][j] = __float_as_uint(ws_lo[off]);
                }
            }
            #pragma unroll
            for (int nt = 0; nt < 4; nt++) {
                int nn = wn * 32 + nt * 8 + rA;
                #pragma unroll
                for (int j = 0; j < 2; j++) {
                    int off = (kb + cA + j * 4) * 72 + nn;
                    bhi[nt][j] = __float_as_uint(hs_hi[off]);
                    blo[nt][j] = __float_as_uint(hs_lo[off]);
                }
            }
            #pragma unroll
            for (int mt = 0; mt < 2; mt++)
                #pragma unroll
                for (int nt = 0; nt < 4; nt++) {
                    mma8(d[mt][nt], ahi[mt], bhi[nt]);
                    mma8(d[mt][nt], ahi[mt], blo[nt]);
                    mma8(d[mt][nt], alo[mt], bhi[nt]);
                }
        }
    }
    __syncthreads();

    float* st = sm;                       // [128][72]
    #pragma unroll
    for (int mt = 0; mt < 2; mt++)
        #pragma unroll
        for (int nt = 0; nt < 4; nt++)
            #pragma unroll
            for (int j = 0; j < 4; j++) {
                int m = wm * 32 + mt * 16 + rA + (j >> 1) * 8;
                int n = wn * 32 + nt * 8 + 2 * cA + (j & 1);
                st[m * 72 + n] = d[mt][nt][j];
            }
    __syncthreads();
    for (int idx = tid; idx < 8192; idx += 256) {
        int b = idx >> 7, rl = idx & 127;
        g_gp[ky][b * 2048 + r0 + rl] = st[rl * 72 + b];
    }
}

// ---------------- kPoint: 8-way partial sum + LSTM + h splits ----------------
__global__ void kPoint(const float* __restrict__ bih, const float* __restrict__ bhh) {
    if (g_done) return;
    int gid = blockIdx.x * blockDim.x + threadIdx.x;
    int b = gid >> 9, u = gid & 511;
    float gate[4];
    #pragma unroll
    for (int q = 0; q < 4; q++) {
        int j = u + 512 * q;
        float s = bih[j] + bhh[j];
        #pragma unroll
        for (int ks = 0; ks < NKS; ks++) s += g_gp[ks][b * 2048 + j];
        gate[q] = s;
    }
    float ii = 1.f / (1.f + expf(-gate[0]));
    float ff = 1.f / (1.f + expf(-gate[1]));
    float gg = tanhf(gate[2]);
    float oo = 1.f / (1.f + expf(-gate[3]));
    float c = ff * g_c[gid] + ii * gg;
    g_c[gid] = c;
    float h = oo * tanhf(c);
    float hi, lo; tf32split(h, hi, lo);
    g_aht[u * 64 + b] = hi; g_alt[u * 64 + b] = lo;
}

// ---------------- kBmma: pipelined tf32-3x logits GEMM ----------------
// grid 250 x 256 thr (8 warps 4m x 2n): tile M=128 vocab x N=64, 16 chunks K=32.
__global__ __launch_bounds__(256) void kBmma(const float* __restrict__ bl,
                                             float* __restrict__ out, int t) {
    extern __shared__ __align__(16) float sm[];
    const int tid = threadIdx.x, lane = tid & 31, wid = tid >> 5;
    const int blk = blockIdx.x;
    const int r0 = blk * 128;

    if (g_done) {
        for (int idx = tid; idx < 128 * 64; idx += 256) {
            int b = idx >> 7, r = idx & 127;
            out[(size_t)b * (TT * VOC) + (size_t)t * VOC + r0 + r] = 0.f;
        }
        return;
    }

    const uint32_t smb = smem_u32(sm);
    const int wm = wid & 3, wn = wid >> 2;
    const int rA = lane >> 2, cA = lane & 3;

    // stage chunk ch into buffer buf via cp.async (one commit group)
    auto stage = [&](int ch, int buf) {
        const int kc0 = ch * 32;
        uint32_t base = smb + buf * BUF_FLOATS * 4;
        #pragma unroll
        for (int it = 0; it < 8; it++) {            // W: 2048 f4 / 256 thr
            int i = tid + it * 256;
            int tile = i >> 10, j = i & 1023, row = j >> 3, c4 = j & 7;
            const float* src = (tile ? g_Wlo : g_Wh)
                             + (size_t)(r0 + row) * 512 + kc0 + c4 * 4;
            cpa16(base + (tile * WS_TILE + row * 40 + c4 * 4) * 4, src);
        }
        #pragma unroll
        for (int it = 0; it < 4; it++) {            // h: 1024 f4 / 256 thr
            int i = tid + it * 256;
            int tile = i >> 9, j = i & 511, k = j >> 4, c4 = j & 15;
            const float* src = (tile ? g_alt : g_aht) + (kc0 + k) * 64 + c4 * 4;
            cpa16(base + (2 * WS_TILE + tile * HS_TILE + k * 72 + c4 * 4) * 4, src);
        }
        asm volatile("cp.async.commit_group;" ::: "memory");
    };

    float d[2][4][4];
    #pragma unroll
    for (int mt = 0; mt < 2; mt++)
        #pragma unroll
        for (int nt = 0; nt < 4; nt++)
            #pragma unroll
            for (int j = 0; j < 4; j++) d[mt][nt][j] = 0.f;

    stage(0, 0);
    stage(1, 1);

    for (int ch = 0; ch < 16; ch++) {
        if (ch < 15) asm volatile("cp.async.wait_group 1;" ::: "memory");
        else         asm volatile("cp.async.wait_group 0;" ::: "memory");
        __syncthreads();

        const float* base  = sm + (ch & 1) * BUF_FLOATS;
        const float* ws_hi = base;
        const float* ws_lo = base + WS_TILE;
        const float* hs_hi = base + 2 * WS_TILE;
        const float* hs_lo = base + 2 * WS_TILE + HS_TILE;

        #pragma unroll
        for (int k8 = 0; k8 < 4; k8++) {
            const int kb = k8 * 8;
            uint32_t ahi[2][4], alo[2][4], bhi[4][2], blo[4][2];
            #pragma unroll
            for (int mt = 0; mt < 2; mt++) {
                int mbase = (wm * 32 + mt * 16) * 40;
                #pragma unroll
                for (int j = 0; j < 4; j++) {
                    int off = mbase + (rA + (j & 1) * 8) * 40 + kb + cA + (j >> 1) * 4;
                    ahi[mt][j] = __float_as_uint(ws_hi[off]);
                    alo[mt][j] = __float_as_uint(ws_lo[off]);
                }
            }
            #pragma unroll
            for (int nt = 0; nt < 4; nt++) {
                int nn = wn * 32 + nt * 8 + rA;
                #pragma unroll
                for (int j = 0; j < 2; j++) {
                    int off = (kb + cA + j * 4) * 72 + nn;
                    bhi[nt][j] = __float_as_uint(hs_hi[off]);
                    blo[nt][j] = __float_as_uint(hs_lo[off]);
                }
            }
            #pragma unroll
            for (int mt = 0; mt < 2; mt++)
                #pragma unroll
                for (int nt = 0; nt < 4; nt++) {
                    mma8(d[mt][nt], ahi[mt], bhi[nt]);
                    mma8(d[mt][nt], ahi[mt], blo[nt]);
                    mma8(d[mt][nt], alo[mt], bhi[nt]);
                }
        }
        __syncthreads();
        if (ch + 2 < 16) stage(ch + 2, ch & 1);
    }
    __syncthreads();

    // stage D to smem st[128][72]
    float* st = sm;
    #pragma unroll
    for (int mt = 0; mt < 2; mt++)
        #pragma unroll
        for (int nt = 0; nt < 4; nt++)
            #pragma unroll
            for (int j = 0; j < 4; j++) {
                int m = wm * 32 + mt * 16 + rA + (j >> 1) * 8;
                int n = wn * 32 + nt * 8 + 2 * cA + (j & 1);
                st[m * 72 + n] = d[mt][nt][j];
            }
    __syncthreads();

    float* cv = sm + 128 * 72;
    int*   ci = reinterpret_cast<int*>(cv + 256);
    {
        int b = tid >> 2, q = tid & 3;            // thread: batch b, rows q*32..q*32+31
        float best = -1e30f; int bi = 0;
        float* op = out + (size_t)b * (TT * VOC) + (size_t)t * VOC + r0 + q * 32;
        #pragma unroll
        for (int g = 0; g < 8; g++) {
            int rb = q * 32 + g * 4;
            float4 v;
            v.x = st[(rb + 0) * 72 + b] + bl[r0 + rb + 0];
            v.y = st[(rb + 1) * 72 + b] + bl[r0 + rb + 1];
            v.z = st[(rb + 2) * 72 + b] + bl[r0 + rb + 2];
            v.w = st[(rb + 3) * 72 + b] + bl[r0 + rb + 3];
            if (v.x > best) { best = v.x; bi = r0 + rb; }
            if (v.y > best) { best = v.y; bi = r0 + rb + 1; }
            if (v.z > best) { best = v.z; bi = r0 + rb + 2; }
            if (v.w > best) { best = v.w; bi = r0 + rb + 3; }
            stcs4(op + g * 4, v);
        }
        cv[tid] = best; ci[tid] = bi;
    }
    __syncthreads();
    if ((tid & 3) == 0) {
        int b = tid >> 2;
        float best = cv[tid]; int bi = ci[tid];
        #pragma unroll
        for (int q = 1; q < 4; q++) {
            float v = cv[tid + q]; int i = ci[tid + q];
            if (v > best || (v == best && i < bi)) { best = v; bi = i; }
        }
        g_pv[blk * 64 + b] = best; g_pi[blk * 64 + b] = bi;
    }
}

// ---------------- kC: argmax finalize (250 partials) ----------------
__global__ __launch_bounds__(512) void kC() {
    if (g_done) return;
    __shared__ float sv[512];
    __shared__ int   si[512];
    __shared__ int   sm2[64];
    int tid = threadIdx.x;
    int b = tid & 63, q = tid >> 6;               // q 0..7, slices of 32
    int s = q * 32, e = (s + 32 < NPART) ? s + 32 : NPART;
    float best = -1e30f; int bi = 0x7fffffff;
    for (int k = s; k < e; k++) {
        float v = g_pv[k * 64 + b];
        int   i = g_pi[k * 64 + b];
        if (v > best || (v == best && i < bi)) { best = v; bi = i; }
    }
    sv[q * 64 + b] = best; si[q * 64 + b] = bi;
    __syncthreads();
    if (tid < 64) {
        float bvv = sv[tid]; int bix = si[tid];
        #pragma unroll
        for (int q2 = 1; q2 < 8; q2++) {
            float v = sv[q2 * 64 + tid]; int i = si[q2 * 64 + tid];
            if (v > bvv || (v == bvv && i < bix)) { bvv = v; bix = i; }
        }
        g_word[tid] = bix;
        int m = g_mask[tid] | (bix == END_TOK);
        g_mask[tid] = m;
        sm2[tid] = m;
    }
    __syncthreads();
    if (tid == 0) {
        int all = 1;
        for (int b2 = 0; b2 < 64; b2++) all &= sm2[b2];
        if (all) g_done = 1;
    }
}

extern "C" void kernel_launch(void* const* d_in, const int* in_sizes, int n_in,
                              void* d_out, int out_size) {
    const float* feat = (const float*)d_in[0];
    const float* emb  = (const float*)d_in[1];
    const float* Wih  = (const float*)d_in[2];
    const float* Whh  = (const float*)d_in[3];
    const float* bih  = (const float*)d_in[4];
    const float* bhh  = (const float*)d_in[5];
    const float* Wl   = (const float*)d_in[6];
    const float* bl   = (const float*)d_in[7];
    float* out = (float*)d_out;

    cudaFuncSetAttribute(kBmma,  cudaFuncAttributeMaxDynamicSharedMemorySize, BMMA_SMEM);
    cudaFuncSetAttribute(kGatesM, cudaFuncAttributeMaxDynamicSharedMemorySize, GATES_SMEM);

    kSplitW<<<VOC * HID / 256, 256>>>(Wl);
    kSplitG<<<2048 * 1024 / 256, 256>>>(Wih, Whh);
    kInit<<<64, 512>>>(feat);
    for (int t = 0; t < TT; t++) {
        kEmb<<<64, 512>>>(emb);
        kGatesM<<<dim3(16, 8), 256, GATES_SMEM>>>();
        kPoint<<<64, 512>>>(bih, bhh);
        kBmma<<<NBLK_B, 256, BMMA_SMEM>>>(bl, out, t);
        kC<<<1, 512>>>();
    }
}